// round 10
// baseline (speedup 1.0000x reference)
#include <cuda_runtime.h>

#define N_DATA 1024
#define D_IN   256
#define H_DIM  384
#define C_OUT  10
#define M_IND  128
#define NT_PTS 256
#define SCALE_K (1.0f/1024.0f)
#define JITTER_K 1e-3f
#define LPACK (M_IND*(M_IND+1)/2)

typedef unsigned long long ull;

// ---------------- device scratch ----------------
__device__ float g_HX[N_DATA*H_DIM];
__device__ float g_SX[N_DATA*H_DIM];
__device__ float g_HZ[M_IND*H_DIM];
__device__ float g_SZ[M_IND*H_DIM];
__device__ float g_HT[NT_PTS*H_DIM];
__device__ float g_ST[NT_PTS*H_DIM];
__device__ float g_LAM[N_DATA*C_OUT];
__device__ float g_Pzx[M_IND*N_DATA];
__device__ float g_Qzx[M_IND*N_DATA];
__device__ float g_Pzz[M_IND*M_IND];
__device__ float g_Qzz[M_IND*M_IND];
__device__ float g_Ptz[NT_PTS*M_IND];
__device__ float g_Qtz[NT_PTS*M_IND];
__device__ float g_Kzx[C_OUT*M_IND*N_DATA];
__device__ float g_Kzz[C_OUT*M_IND*M_IND];
__device__ float g_Ktz[C_OUT*NT_PTS*M_IND];
__device__ float g_Bpart[4*C_OUT*M_IND*M_IND];
__device__ float g_LKzz[C_OUT*LPACK];
__device__ float g_LB[C_OUT*LPACK];
__device__ float g_alpha[C_OUT*M_IND];
__device__ float g_cvec[C_OUT*M_IND];
__device__ float g_SSZ[C_OUT*NT_PTS];
__device__ float g_SSB[C_OUT*NT_PTS];

// ---------------- f32x2 packed helpers ----------------
__device__ __forceinline__ ull dup2(float x) {
    ull r; unsigned u = __float_as_uint(x);
    asm("mov.b64 %0, {%1, %1};" : "=l"(r) : "r"(u));
    return r;
}
__device__ __forceinline__ void fma2(ull& d, ull a, ull b) {
    asm("fma.rn.f32x2 %0, %1, %2, %0;" : "+l"(d) : "l"(a), "l"(b));
}
__device__ __forceinline__ float2 unp(ull v) {
    float2 f;
    asm("mov.b64 {%0, %1}, %2;" : "=f"(f.x), "=f"(f.y) : "l"(v));
    return f;
}

// =============== fused forward: H/S for X, Z, T (one launch) ===============
__global__ void fwd_all(const float* __restrict__ X, const float* __restrict__ Z,
                        const float* __restrict__ T, const float* __restrict__ W1,
                        const float* __restrict__ b1) {
    __shared__ __align__(16) float As[16][68];
    __shared__ __align__(16) float Bs[16][68];
    const int tid = threadIdx.x;
    const int rb = blockIdx.y, nb = blockIdx.x;
    const float* src; float* Hd; float* Sd; int row0;
    if (rb < 16)      { src = X; Hd = g_HX; Sd = g_SX; row0 = rb*64; }
    else if (rb < 18) { src = Z; Hd = g_HZ; Sd = g_SZ; row0 = (rb-16)*64; }
    else              { src = T; Hd = g_HT; Sd = g_ST; row0 = (rb-18)*64; }
    const int lrow = tid >> 1, lk = (tid & 1) << 3;
    const int kr = tid >> 3, nq = (tid & 7) << 3;
    const int tx = tid & 15, ty = tid >> 4;
    float acc[8][4] = {};
    for (int k0 = 0; k0 < D_IN; k0 += 16) {
        float4 a0 = *(const float4*)&src[(row0+lrow)*D_IN + k0 + lk];
        float4 a1 = *(const float4*)&src[(row0+lrow)*D_IN + k0 + lk + 4];
        float4 b0 = *(const float4*)&W1[(k0+kr)*H_DIM + nb*64 + nq];
        float4 b1v= *(const float4*)&W1[(k0+kr)*H_DIM + nb*64 + nq + 4];
        __syncthreads();
        As[lk+0][lrow]=a0.x; As[lk+1][lrow]=a0.y; As[lk+2][lrow]=a0.z; As[lk+3][lrow]=a0.w;
        As[lk+4][lrow]=a1.x; As[lk+5][lrow]=a1.y; As[lk+6][lrow]=a1.z; As[lk+7][lrow]=a1.w;
        *(float4*)&Bs[kr][nq] = b0; *(float4*)&Bs[kr][nq+4] = b1v;
        __syncthreads();
        #pragma unroll
        for (int kk = 0; kk < 16; ++kk) {
            float4 a4 = *(const float4*)&As[kk][ty*8];
            float4 a5 = *(const float4*)&As[kk][ty*8+4];
            float4 b4 = *(const float4*)&Bs[kk][tx*4];
            float a[8] = {a4.x,a4.y,a4.z,a4.w,a5.x,a5.y,a5.z,a5.w};
            float b[4] = {b4.x,b4.y,b4.z,b4.w};
            #pragma unroll
            for (int u = 0; u < 8; ++u)
                #pragma unroll
                for (int v = 0; v < 4; ++v) acc[u][v] = fmaf(a[u], b[v], acc[u][v]);
        }
    }
    const int n0 = nb*64 + tx*4;
    float4 bv = *(const float4*)&b1[n0];
    #pragma unroll
    for (int u = 0; u < 8; ++u) {
        int m = row0 + ty*8 + u;
        float4 h4, s4;
        h4.x = tanhf(acc[u][0]+bv.x); h4.y = tanhf(acc[u][1]+bv.y);
        h4.z = tanhf(acc[u][2]+bv.z); h4.w = tanhf(acc[u][3]+bv.w);
        s4.x = 1.f-h4.x*h4.x; s4.y = 1.f-h4.y*h4.y;
        s4.z = 1.f-h4.z*h4.z; s4.w = 1.f-h4.w*h4.w;
        *(float4*)&Hd[m*H_DIM + n0] = h4;
        *(float4*)&Sd[m*H_DIM + n0] = s4;
    }
}

// =============== lambda1 = F + Y ===============
__global__ void lam_kernel(const float* __restrict__ Y, const float* __restrict__ W2,
                           const float* __restrict__ b2) {
    int warp = threadIdx.x >> 5, lane = threadIdx.x & 31;
    int row = blockIdx.x * 8 + warp;
    float h[12];
    #pragma unroll
    for (int r = 0; r < 12; ++r) h[r] = g_HX[row*H_DIM + lane + r*32];
    #pragma unroll
    for (int c = 0; c < C_OUT; ++c) {
        float acc = 0.f;
        #pragma unroll
        for (int r = 0; r < 12; ++r) acc += h[r] * W2[(lane + r*32)*C_OUT + c];
        #pragma unroll
        for (int o = 16; o; o >>= 1) acc += __shfl_down_sync(0xffffffffu, acc, o);
        if (lane == 0) g_LAM[row*C_OUT + c] = acc + b2[c] + Y[row*C_OUT + c];
    }
}

// =============== P and Q grams, all pairs, split into 88 jobs ===============
__global__ void pq_all(const float* __restrict__ X, const float* __restrict__ Z,
                       const float* __restrict__ T) {
    __shared__ __align__(16) float As[16][68];
    __shared__ __align__(16) float Bs[16][68];
    const int tid = threadIdx.x;
    int j = blockIdx.x;
    const int isQ = (j >= 44); if (isQ) j -= 44;
    const float *Ap, *Bp; float* outp; int Nc, mt, nt;
    if (j < 32)      { mt=j>>4;      nt=j&15;     Ap=isQ?Z:g_HZ; Bp=isQ?X:g_HX; outp=isQ?g_Qzx:g_Pzx; Nc=N_DATA; }
    else if (j < 36) { mt=(j-32)>>1; nt=(j-32)&1; Ap=isQ?Z:g_HZ; Bp=isQ?Z:g_HZ; outp=isQ?g_Qzz:g_Pzz; Nc=M_IND; }
    else             { mt=(j-36)>>1; nt=(j-36)&1; Ap=isQ?T:g_HT; Bp=isQ?Z:g_HZ; outp=isQ?g_Qtz:g_Ptz; Nc=M_IND; }
    const int K = isQ ? D_IN : H_DIM;
    const int bm = mt*64, bn = nt*64;
    const int lrow = tid >> 1, lk = (tid & 1) << 3;
    const int tx = tid & 15, ty = tid >> 4;
    float acc[8][4] = {};
    for (int k0 = 0; k0 < K; k0 += 16) {
        float4 a0 = *(const float4*)&Ap[(bm+lrow)*K + k0 + lk];
        float4 a1 = *(const float4*)&Ap[(bm+lrow)*K + k0 + lk + 4];
        float4 b0 = *(const float4*)&Bp[(bn+lrow)*K + k0 + lk];
        float4 b1 = *(const float4*)&Bp[(bn+lrow)*K + k0 + lk + 4];
        __syncthreads();
        As[lk+0][lrow]=a0.x; As[lk+1][lrow]=a0.y; As[lk+2][lrow]=a0.z; As[lk+3][lrow]=a0.w;
        As[lk+4][lrow]=a1.x; As[lk+5][lrow]=a1.y; As[lk+6][lrow]=a1.z; As[lk+7][lrow]=a1.w;
        Bs[lk+0][lrow]=b0.x; Bs[lk+1][lrow]=b0.y; Bs[lk+2][lrow]=b0.z; Bs[lk+3][lrow]=b0.w;
        Bs[lk+4][lrow]=b1.x; Bs[lk+5][lrow]=b1.y; Bs[lk+6][lrow]=b1.z; Bs[lk+7][lrow]=b1.w;
        __syncthreads();
        #pragma unroll
        for (int kk = 0; kk < 16; ++kk) {
            float4 a4 = *(const float4*)&As[kk][ty*8];
            float4 a5 = *(const float4*)&As[kk][ty*8+4];
            float4 b4 = *(const float4*)&Bs[kk][tx*4];
            float a[8] = {a4.x,a4.y,a4.z,a4.w,a5.x,a5.y,a5.z,a5.w};
            float b[4] = {b4.x,b4.y,b4.z,b4.w};
            #pragma unroll
            for (int u = 0; u < 8; ++u)
                #pragma unroll
                for (int v = 0; v < 4; ++v) acc[u][v] = fmaf(a[u], b[v], acc[u][v]);
        }
    }
    const int n0 = bn + tx*4;
    #pragma unroll
    for (int u = 0; u < 8; ++u) {
        int m = bm + ty*8 + u;
        float4 o4 = {acc[u][0]+1.f, acc[u][1]+1.f, acc[u][2]+1.f, acc[u][3]+1.f};
        *(float4*)&outp[(size_t)m*Nc + n0] = o4;
    }
}

// =============== all 30 K matrices (220 jobs): 64x128 tile, 8x8/thread FFMA2 ===============
// 4 row-pairs (LDS.64 direct) x 8 cols (dup2), 1.0 B/MAC smem traffic.
__global__ void __launch_bounds__(128) kbuild_all(const float* __restrict__ W2) {
    __shared__ __align__(16) float As[16][68];
    __shared__ __align__(16) float Bs[16][132];
    __shared__ float ws[H_DIM];
    const int tid = threadIdx.x;
    const int j = blockIdx.x;
    const float *Sa, *Sb, *Pp, *Qp; float* Kout; int Nc, mt, nt, i, jit;
    if (j < 160)      { i=j>>4; int r=j&15; mt=r>>3; nt=r&7; Sa=g_SZ; Sb=g_SX; Pp=g_Pzx; Qp=g_Qzx; Kout=g_Kzx+(size_t)i*M_IND*N_DATA; Nc=N_DATA; jit=0; }
    else if (j < 180) { int q=j-160; i=q>>1; mt=q&1; nt=0; Sa=g_SZ; Sb=g_SZ; Pp=g_Pzz; Qp=g_Qzz; Kout=g_Kzz+(size_t)i*M_IND*M_IND; Nc=M_IND; jit=1; }
    else              { int q=j-180; i=q>>2; mt=q&3; nt=0; Sa=g_ST; Sb=g_SZ; Pp=g_Ptz; Qp=g_Qtz; Kout=g_Ktz+(size_t)i*NT_PTS*M_IND; Nc=M_IND; jit=0; }
    for (int k = tid; k < H_DIM; k += 128) { float w = W2[k*C_OUT + i]; ws[k] = w*w; }
    const int bm = mt*64, bn = nt*128;
    const int lrow = tid >> 1, lk = (tid & 1) << 3;   // A loader: 64 rows x 16k
    const int tx = tid & 15, ty = tid >> 4;
    ull accp[4][8] = {};   // [row-pair p][col v]
    for (int k0 = 0; k0 < H_DIM; k0 += 16) {
        float4 a0 = *(const float4*)&Sa[(bm+lrow)*H_DIM + k0 + lk];
        float4 a1 = *(const float4*)&Sa[(bm+lrow)*H_DIM + k0 + lk + 4];
        // B loader: each thread owns one of 128 cols, 16 k values
        const float* brow = &Sb[(bn+tid)*H_DIM + k0];
        float4 q0 = *(const float4*)&brow[0];
        float4 q1 = *(const float4*)&brow[4];
        float4 q2 = *(const float4*)&brow[8];
        float4 q3 = *(const float4*)&brow[12];
        __syncthreads();
        As[lk+0][lrow]=a0.x*ws[k0+lk+0]; As[lk+1][lrow]=a0.y*ws[k0+lk+1];
        As[lk+2][lrow]=a0.z*ws[k0+lk+2]; As[lk+3][lrow]=a0.w*ws[k0+lk+3];
        As[lk+4][lrow]=a1.x*ws[k0+lk+4]; As[lk+5][lrow]=a1.y*ws[k0+lk+5];
        As[lk+6][lrow]=a1.z*ws[k0+lk+6]; As[lk+7][lrow]=a1.w*ws[k0+lk+7];
        Bs[0][tid]=q0.x;  Bs[1][tid]=q0.y;  Bs[2][tid]=q0.z;  Bs[3][tid]=q0.w;
        Bs[4][tid]=q1.x;  Bs[5][tid]=q1.y;  Bs[6][tid]=q1.z;  Bs[7][tid]=q1.w;
        Bs[8][tid]=q2.x;  Bs[9][tid]=q2.y;  Bs[10][tid]=q2.z; Bs[11][tid]=q2.w;
        Bs[12][tid]=q3.x; Bs[13][tid]=q3.y; Bs[14][tid]=q3.z; Bs[15][tid]=q3.w;
        __syncthreads();
        #pragma unroll
        for (int kk = 0; kk < 16; ++kk) {
            ull ap[4];
            ap[0] = *(const ull*)&As[kk][ty*8 + 0];
            ap[1] = *(const ull*)&As[kk][ty*8 + 2];
            ap[2] = *(const ull*)&As[kk][ty*8 + 4];
            ap[3] = *(const ull*)&As[kk][ty*8 + 6];
            float4 b0 = *(const float4*)&Bs[kk][tx*8];
            float4 b1 = *(const float4*)&Bs[kk][tx*8 + 4];
            ull db[8] = {dup2(b0.x), dup2(b0.y), dup2(b0.z), dup2(b0.w),
                         dup2(b1.x), dup2(b1.y), dup2(b1.z), dup2(b1.w)};
            #pragma unroll
            for (int p = 0; p < 4; ++p)
                #pragma unroll
                for (int v = 0; v < 8; ++v) fma2(accp[p][v], ap[p], db[v]);
        }
    }
    const int n0 = bn + tx*8;
    #pragma unroll
    for (int p = 0; p < 4; ++p) {
        float2 cc[8];
        #pragma unroll
        for (int v = 0; v < 8; ++v) cc[v] = unp(accp[p][v]);
        #pragma unroll
        for (int h = 0; h < 2; ++h) {
            int m = bm + ty*8 + 2*p + h;
            const float* Pr = &Pp[(size_t)m*Nc + n0];
            const float* Qr = &Qp[(size_t)m*Nc + n0];
            float4 p0 = *(const float4*)&Pr[0];
            float4 p1 = *(const float4*)&Pr[4];
            float4 q0 = *(const float4*)&Qr[0];
            float4 q1 = *(const float4*)&Qr[4];
            float pv[8] = {p0.x,p0.y,p0.z,p0.w,p1.x,p1.y,p1.z,p1.w};
            float qv[8] = {q0.x,q0.y,q0.z,q0.w,q1.x,q1.y,q1.z,q1.w};
            float o[8];
            #pragma unroll
            for (int v = 0; v < 8; ++v) {
                float uu = h ? cc[v].y : cc[v].x;
                o[v] = SCALE_K * (pv[v] + qv[v]*uu);
                if (jit && m == n0 + v) o[v] += JITTER_K;
            }
            float* Kr = &Kout[(size_t)m*Nc + n0];
            *(float4*)&Kr[0] = make_float4(o[0],o[1],o[2],o[3]);
            *(float4*)&Kr[4] = make_float4(o[4],o[5],o[6],o[7]);
        }
    }
}

// =============== Bpart (split-K of 2*Kzx@Kzx^T) + alpha, FFMA2 inner ===============
__global__ void bgemm_alpha() {
    const int tid = threadIdx.x;
    const int j = blockIdx.x;
    if (j < 160) {
        __shared__ __align__(16) float As[16][68];
        __shared__ __align__(16) float Bs[16][68];
        int i = j >> 4, r = j & 15;
        int kc = r >> 2, mt = (r >> 1) & 1, nt = r & 1;
        const float* A = g_Kzx + (size_t)i*M_IND*N_DATA;
        const int bm = mt*64, bn = nt*64, kbeg = kc*256;
        const int lrow = tid >> 1, lk = (tid & 1) << 3;
        const int tx = tid & 15, ty = tid >> 4;
        ull accp[4][4] = {};
        for (int k0 = kbeg; k0 < kbeg+256; k0 += 16) {
            float4 a0 = *(const float4*)&A[(bm+lrow)*N_DATA + k0 + lk];
            float4 a1 = *(const float4*)&A[(bm+lrow)*N_DATA + k0 + lk + 4];
            float4 b0 = *(const float4*)&A[(bn+lrow)*N_DATA + k0 + lk];
            float4 b1 = *(const float4*)&A[(bn+lrow)*N_DATA + k0 + lk + 4];
            __syncthreads();
            As[lk+0][lrow]=a0.x; As[lk+1][lrow]=a0.y; As[lk+2][lrow]=a0.z; As[lk+3][lrow]=a0.w;
            As[lk+4][lrow]=a1.x; As[lk+5][lrow]=a1.y; As[lk+6][lrow]=a1.z; As[lk+7][lrow]=a1.w;
            Bs[lk+0][lrow]=b0.x; Bs[lk+1][lrow]=b0.y; Bs[lk+2][lrow]=b0.z; Bs[lk+3][lrow]=b0.w;
            Bs[lk+4][lrow]=b1.x; Bs[lk+5][lrow]=b1.y; Bs[lk+6][lrow]=b1.z; Bs[lk+7][lrow]=b1.w;
            __syncthreads();
            #pragma unroll
            for (int kk = 0; kk < 16; ++kk) {
                ull ap[4];
                ap[0] = *(const ull*)&As[kk][ty*8 + 0];
                ap[1] = *(const ull*)&As[kk][ty*8 + 2];
                ap[2] = *(const ull*)&As[kk][ty*8 + 4];
                ap[3] = *(const ull*)&As[kk][ty*8 + 6];
                float4 b4 = *(const float4*)&Bs[kk][tx*4];
                ull db[4] = {dup2(b4.x), dup2(b4.y), dup2(b4.z), dup2(b4.w)};
                #pragma unroll
                for (int p = 0; p < 4; ++p)
                    #pragma unroll
                    for (int v = 0; v < 4; ++v) fma2(accp[p][v], ap[p], db[v]);
            }
        }
        float* outp = g_Bpart + ((size_t)(kc*C_OUT + i)*M_IND)*M_IND;
        const int n0 = bn + tx*4;
        #pragma unroll
        for (int p = 0; p < 4; ++p) {
            float2 c0 = unp(accp[p][0]);
            float2 c1 = unp(accp[p][1]);
            float2 c2 = unp(accp[p][2]);
            float2 c3 = unp(accp[p][3]);
            int m = bm + ty*8 + 2*p;
            *(float4*)&outp[m*M_IND + n0] =
                make_float4(2.f*c0.x, 2.f*c1.x, 2.f*c2.x, 2.f*c3.x);
            *(float4*)&outp[(m+1)*M_IND + n0] =
                make_float4(2.f*c0.y, 2.f*c1.y, 2.f*c2.y, 2.f*c3.y);
        }
    } else {
        int k = j - 160;
        int i = k >> 2, rb = (k & 3) * 32;
        int w = tid >> 5, lane = tid & 31;
        #pragma unroll
        for (int rr = 0; rr < 8; ++rr) {
            int m = rb + w*8 + rr;
            const float* row = g_Kzx + ((size_t)i*M_IND + m)*N_DATA;
            float acc = 0.f;
            for (int n = lane; n < N_DATA; n += 32) acc += row[n] * g_LAM[n*C_OUT + i];
            #pragma unroll
            for (int o = 16; o; o >>= 1) acc += __shfl_down_sync(0xffffffffu, acc, o);
            if (lane == 0) g_alpha[i*M_IND + m] = acc;
        }
    }
}

// =============== register-tiled right-looking Cholesky (no spills) ===============
__global__ void __launch_bounds__(256) chol_all() {
    const int s = blockIdx.x, tid = threadIdx.x;
    const int isB = (s >= C_OUT);
    const int i = isB ? s - C_OUT : s;
    const float* A0 = g_Kzz + (size_t)i*M_IND*M_IND;
    const int tr = tid >> 4, tc = tid & 15;
    const int r0 = tr*8, c0 = tc*8;
    float a[8][8];
    #pragma unroll
    for (int u = 0; u < 8; ++u) {
        #pragma unroll
        for (int v = 0; v < 8; v += 4) {
            float4 x = *(const float4*)&A0[(r0+u)*M_IND + c0 + v];
            a[u][v]=x.x; a[u][v+1]=x.y; a[u][v+2]=x.z; a[u][v+3]=x.w;
            if (isB) {
                #pragma unroll
                for (int p = 0; p < 4; ++p) {
                    float4 y = *(const float4*)&g_Bpart[((size_t)(p*C_OUT+i)*M_IND + r0+u)*M_IND + c0+v];
                    a[u][v]+=y.x; a[u][v+1]+=y.y; a[u][v+2]+=y.z; a[u][v+3]+=y.w;
                }
            }
        }
    }
    __shared__ float colbuf[2][M_IND];
    for (int jb = 0; jb < 16; ++jb) {
        const bool owner = (tc == jb);
        #pragma unroll
        for (int v = 0; v < 8; ++v) {
            const int j = jb*8 + v;
            float* col = colbuf[v & 1];
            if (owner) {
                #pragma unroll
                for (int u = 0; u < 8; ++u) col[r0 + u] = a[u][v];
            }
            __syncthreads();
            const float djj = col[j];
            const float dinv = rsqrtf(djj);
            float ci[8], ck[8];
            #pragma unroll
            for (int u = 0; u < 8; ++u) {
                int ri = r0 + u;
                ci[u] = (ri > j) ? col[ri] * dinv : 0.f;
            }
            #pragma unroll
            for (int w = 0; w < 8; ++w) {
                int kk = c0 + w;
                ck[w] = (kk > j) ? col[kk] * dinv : 0.f;
            }
            if (owner) {
                #pragma unroll
                for (int u = 0; u < 8; ++u) {
                    int ri = r0 + u;
                    if (ri > j)       a[u][v] = ci[u];
                    else if (ri == j) a[u][v] = djj * dinv;
                }
            }
            #pragma unroll
            for (int u = 0; u < 8; ++u)
                #pragma unroll
                for (int w = 0; w < 8; ++w)
                    a[u][w] = fmaf(-ci[u], ck[w], a[u][w]);
        }
    }
    float* out = isB ? (g_LB + i*LPACK) : (g_LKzz + i*LPACK);
    if (c0 <= r0 + 7) {
        #pragma unroll
        for (int u = 0; u < 8; ++u) {
            int ri = r0 + u;
            if (ri >= c0) {
                int base = (ri*(ri+1)) >> 1;
                #pragma unroll
                for (int w = 0; w < 8; ++w) {
                    int kk = c0 + w;
                    if (kk <= ri) out[base + kk] = a[u][w];
                }
            }
        }
    }
}

// =============== solves: 640 fs blocks + 10 meansolve blocks ===============
__global__ void solve_all() {
    __shared__ float Lp[LPACK];
    __shared__ float dinv[M_IND];
    __shared__ float ysm[M_IND];
    const int b = blockIdx.x, tid = threadIdx.x;
    const int w = tid >> 5, lane = tid & 31;
    if (b < 640) {
        const int s = b >> 5;
        const int t = (b & 31)*8 + w;
        const int i = (s < C_OUT) ? s : s - C_OUT;
        const float* Ls = (s < C_OUT) ? (g_LKzz + s*LPACK) : (g_LB + (s-C_OUT)*LPACK);
        for (int idx = tid; idx < LPACK; idx += 256) Lp[idx] = Ls[idx];
        if (tid < M_IND) dinv[tid] = 1.0f / Ls[((tid*(tid+1))>>1) + tid];
        __syncthreads();
        const float* bvec = g_Ktz + ((size_t)i*NT_PTS + t)*M_IND;
        float br[4]; int base[4];
        #pragma unroll
        for (int r = 0; r < 4; ++r) {
            br[r] = bvec[lane + 32*r];
            int row = r*32 + lane;
            base[r] = (row*(row+1)) >> 1;
        }
        float ss = 0.f;
        #pragma unroll
        for (int oreg = 0; oreg < 4; ++oreg) {
            for (int jj = 0; jj < 32; ++jj) {
                int jc = oreg*32 + jj;
                float yj = __shfl_sync(0xffffffffu, br[oreg], jj) * dinv[jc];
                ss = fmaf(yj, yj, ss);
                if (lane > jj) br[oreg] -= Lp[base[oreg] + jc] * yj;
                #pragma unroll
                for (int r = oreg+1; r < 4; ++r) br[r] -= Lp[base[r] + jc] * yj;
            }
        }
        if (lane == 0) {
            if (s < C_OUT) g_SSZ[i*NT_PTS + t] = ss;
            else           g_SSB[i*NT_PTS + t] = ss;
        }
    } else {
        const int i = b - 640;
        const float* Ls = g_LB + i*LPACK;
        for (int idx = tid; idx < LPACK; idx += 256) Lp[idx] = Ls[idx];
        if (tid < M_IND) dinv[tid] = 1.0f / Ls[((tid*(tid+1))>>1) + tid];
        __syncthreads();
        if (w != 0) return;
        float br[4]; int base[4];
        #pragma unroll
        for (int r = 0; r < 4; ++r) {
            br[r] = g_alpha[i*M_IND + lane + 32*r];
            int row = r*32 + lane;
            base[r] = (row*(row+1)) >> 1;
        }
        #pragma unroll
        for (int oreg = 0; oreg < 4; ++oreg) {
            for (int jj = 0; jj < 32; ++jj) {
                int jc = oreg*32 + jj;
                float yj = __shfl_sync(0xffffffffu, br[oreg], jj) * dinv[jc];
                if (lane == 0) ysm[jc] = yj;
                if (lane > jj) br[oreg] -= Lp[base[oreg] + jc] * yj;
                #pragma unroll
                for (int r = oreg+1; r < 4; ++r) br[r] -= Lp[base[r] + jc] * yj;
            }
        }
        __syncwarp();
        float xr[4];
        #pragma unroll
        for (int r = 0; r < 4; ++r) xr[r] = ysm[r*32 + lane];
        #pragma unroll
        for (int oreg = 3; oreg >= 0; --oreg) {
            for (int jj = 31; jj >= 0; --jj) {
                int jc = oreg*32 + jj;
                float xj = __shfl_sync(0xffffffffu, xr[oreg], jj) * dinv[jc];
                if (lane == 0) g_cvec[i*M_IND + jc] = xj;
                int rb2 = (jc*(jc+1)) >> 1;
                if (lane < jj) xr[oreg] -= Lp[rb2 + oreg*32 + lane] * xj;
                #pragma unroll
                for (int r = 0; r < 4; ++r)
                    if (r < oreg) xr[r] -= Lp[rb2 + r*32 + lane] * xj;
            }
        }
    }
}

// =============== epilogue: mean + variance ===============
__global__ void epilogue(const float* __restrict__ Xt, const float* __restrict__ W2,
                         float* __restrict__ out) {
    const int gw = blockIdx.x*8 + (threadIdx.x >> 5);
    const int lane = threadIdx.x & 31;
    const int t = gw / C_OUT, i = gw - t*C_OUT;
    float accU = 0.f, ph = 0.f, qx = 0.f;
    for (int k = lane; k < H_DIM; k += 32) {
        float s = g_ST[t*H_DIM + k];
        float h = g_HT[t*H_DIM + k];
        float w = W2[k*C_OUT + i];
        accU = fmaf(s*s, w*w, accU);
        ph = fmaf(h, h, ph);
    }
    for (int k = lane; k < D_IN; k += 32) { float x = Xt[t*D_IN + k]; qx = fmaf(x, x, qx); }
    float mean = 0.f;
    const float* kr = g_Ktz + ((size_t)i*NT_PTS + t)*M_IND;
    const float* cr = g_cvec + i*M_IND;
    #pragma unroll
    for (int r = 0; r < 4; ++r) mean += kr[lane + 32*r] * cr[lane + 32*r];
    #pragma unroll
    for (int o = 16; o; o >>= 1) {
        accU += __shfl_xor_sync(0xffffffffu, accU, o);
        ph   += __shfl_xor_sync(0xffffffffu, ph, o);
        qx   += __shfl_xor_sync(0xffffffffu, qx, o);
        mean += __shfl_xor_sync(0xffffffffu, mean, o);
    }
    if (lane == 0) {
        float kttd = SCALE_K * ((ph + 1.f) + (qx + 1.f)*accU);
        out[t*C_OUT + i] = mean;
        out[NT_PTS*C_OUT + t*C_OUT + i] = kttd - g_SSZ[i*NT_PTS + t] + g_SSB[i*NT_PTS + t];
    }
}

extern "C" void kernel_launch(void* const* d_in, const int* in_sizes, int n_in,
                              void* d_out, int out_size) {
    const float* X  = (const float*)d_in[0];
    const float* Y  = (const float*)d_in[1];
    const float* Z  = (const float*)d_in[2];
    const float* Xt = (const float*)d_in[3];
    const float* W1 = (const float*)d_in[4];
    const float* b1 = (const float*)d_in[5];
    const float* W2 = (const float*)d_in[6];
    const float* b2 = (const float*)d_in[7];
    float* out = (float*)d_out;

    fwd_all<<<dim3(6,22), 128>>>(X, Z, Xt, W1, b1);
    lam_kernel<<<128, 256>>>(Y, W2, b2);
    pq_all<<<88, 128>>>(X, Z, Xt);
    kbuild_all<<<220, 128>>>(W2);
    bgemm_alpha<<<200, 128>>>();
    chol_all<<<20, 256>>>();
    solve_all<<<650, 256>>>();
    epilogue<<<320, 256>>>(Xt, W2, out);
}

// round 11
// speedup vs baseline: 1.1128x; 1.1128x over previous
#include <cuda_runtime.h>

#define N_DATA 1024
#define D_IN   256
#define H_DIM  384
#define C_OUT  10
#define M_IND  128
#define NT_PTS 256
#define SCALE_K (1.0f/1024.0f)
#define JITTER_K 1e-3f
#define LPACK (M_IND*(M_IND+1)/2)

typedef unsigned long long ull;

// ---------------- device scratch ----------------
__device__ float g_HX[N_DATA*H_DIM];
__device__ float g_SX[N_DATA*H_DIM];
__device__ float g_HZ[M_IND*H_DIM];
__device__ float g_SZ[M_IND*H_DIM];
__device__ float g_HT[NT_PTS*H_DIM];
__device__ float g_ST[NT_PTS*H_DIM];
__device__ float g_LAM[N_DATA*C_OUT];
__device__ float g_Pzx[M_IND*N_DATA];
__device__ float g_Qzx[M_IND*N_DATA];
__device__ float g_Pzz[M_IND*M_IND];
__device__ float g_Qzz[M_IND*M_IND];
__device__ float g_Ptz[NT_PTS*M_IND];
__device__ float g_Qtz[NT_PTS*M_IND];
__device__ float g_Kzx[C_OUT*M_IND*N_DATA];
__device__ float g_Kzz[C_OUT*M_IND*M_IND];
__device__ float g_Ktz[C_OUT*NT_PTS*M_IND];
__device__ float g_Bpart[4*C_OUT*M_IND*M_IND];
__device__ float g_LKzz[C_OUT*LPACK];
__device__ float g_LB[C_OUT*LPACK];
__device__ float g_alpha[C_OUT*M_IND];
__device__ float g_cvec[C_OUT*M_IND];
__device__ float g_SSZ[C_OUT*NT_PTS];
__device__ float g_SSB[C_OUT*NT_PTS];

// ---------------- f32x2 packed helpers ----------------
__device__ __forceinline__ ull dup2(float x) {
    ull r; unsigned u = __float_as_uint(x);
    asm("mov.b64 %0, {%1, %1};" : "=l"(r) : "r"(u));
    return r;
}
__device__ __forceinline__ void fma2(ull& d, ull a, ull b) {
    asm("fma.rn.f32x2 %0, %1, %2, %0;" : "+l"(d) : "l"(a), "l"(b));
}
__device__ __forceinline__ float2 unp(ull v) {
    float2 f;
    asm("mov.b64 {%0, %1}, %2;" : "=f"(f.x), "=f"(f.y) : "l"(v));
    return f;
}

// =============== fused forward: H/S for X, Z, T (one launch) ===============
__global__ void fwd_all(const float* __restrict__ X, const float* __restrict__ Z,
                        const float* __restrict__ T, const float* __restrict__ W1,
                        const float* __restrict__ b1) {
    __shared__ __align__(16) float As[16][68];
    __shared__ __align__(16) float Bs[16][68];
    const int tid = threadIdx.x;
    const int rb = blockIdx.y, nb = blockIdx.x;
    const float* src; float* Hd; float* Sd; int row0;
    if (rb < 16)      { src = X; Hd = g_HX; Sd = g_SX; row0 = rb*64; }
    else if (rb < 18) { src = Z; Hd = g_HZ; Sd = g_SZ; row0 = (rb-16)*64; }
    else              { src = T; Hd = g_HT; Sd = g_ST; row0 = (rb-18)*64; }
    const int lrow = tid >> 1, lk = (tid & 1) << 3;
    const int kr = tid >> 3, nq = (tid & 7) << 3;
    const int tx = tid & 15, ty = tid >> 4;
    float acc[8][4] = {};
    for (int k0 = 0; k0 < D_IN; k0 += 16) {
        float4 a0 = *(const float4*)&src[(row0+lrow)*D_IN + k0 + lk];
        float4 a1 = *(const float4*)&src[(row0+lrow)*D_IN + k0 + lk + 4];
        float4 b0 = *(const float4*)&W1[(k0+kr)*H_DIM + nb*64 + nq];
        float4 b1v= *(const float4*)&W1[(k0+kr)*H_DIM + nb*64 + nq + 4];
        __syncthreads();
        As[lk+0][lrow]=a0.x; As[lk+1][lrow]=a0.y; As[lk+2][lrow]=a0.z; As[lk+3][lrow]=a0.w;
        As[lk+4][lrow]=a1.x; As[lk+5][lrow]=a1.y; As[lk+6][lrow]=a1.z; As[lk+7][lrow]=a1.w;
        *(float4*)&Bs[kr][nq] = b0; *(float4*)&Bs[kr][nq+4] = b1v;
        __syncthreads();
        #pragma unroll
        for (int kk = 0; kk < 16; ++kk) {
            float4 a4 = *(const float4*)&As[kk][ty*8];
            float4 a5 = *(const float4*)&As[kk][ty*8+4];
            float4 b4 = *(const float4*)&Bs[kk][tx*4];
            float a[8] = {a4.x,a4.y,a4.z,a4.w,a5.x,a5.y,a5.z,a5.w};
            float b[4] = {b4.x,b4.y,b4.z,b4.w};
            #pragma unroll
            for (int u = 0; u < 8; ++u)
                #pragma unroll
                for (int v = 0; v < 4; ++v) acc[u][v] = fmaf(a[u], b[v], acc[u][v]);
        }
    }
    const int n0 = nb*64 + tx*4;
    float4 bv = *(const float4*)&b1[n0];
    #pragma unroll
    for (int u = 0; u < 8; ++u) {
        int m = row0 + ty*8 + u;
        float4 h4, s4;
        h4.x = tanhf(acc[u][0]+bv.x); h4.y = tanhf(acc[u][1]+bv.y);
        h4.z = tanhf(acc[u][2]+bv.z); h4.w = tanhf(acc[u][3]+bv.w);
        s4.x = 1.f-h4.x*h4.x; s4.y = 1.f-h4.y*h4.y;
        s4.z = 1.f-h4.z*h4.z; s4.w = 1.f-h4.w*h4.w;
        *(float4*)&Hd[m*H_DIM + n0] = h4;
        *(float4*)&Sd[m*H_DIM + n0] = s4;
    }
}

// =============== lambda1 = F + Y ===============
__global__ void lam_kernel(const float* __restrict__ Y, const float* __restrict__ W2,
                           const float* __restrict__ b2) {
    int warp = threadIdx.x >> 5, lane = threadIdx.x & 31;
    int row = blockIdx.x * 8 + warp;
    float h[12];
    #pragma unroll
    for (int r = 0; r < 12; ++r) h[r] = g_HX[row*H_DIM + lane + r*32];
    #pragma unroll
    for (int c = 0; c < C_OUT; ++c) {
        float acc = 0.f;
        #pragma unroll
        for (int r = 0; r < 12; ++r) acc += h[r] * W2[(lane + r*32)*C_OUT + c];
        #pragma unroll
        for (int o = 16; o; o >>= 1) acc += __shfl_down_sync(0xffffffffu, acc, o);
        if (lane == 0) g_LAM[row*C_OUT + c] = acc + b2[c] + Y[row*C_OUT + c];
    }
}

// =============== P and Q grams, all pairs, split into 88 jobs ===============
__global__ void pq_all(const float* __restrict__ X, const float* __restrict__ Z,
                       const float* __restrict__ T) {
    __shared__ __align__(16) float As[16][68];
    __shared__ __align__(16) float Bs[16][68];
    const int tid = threadIdx.x;
    int j = blockIdx.x;
    const int isQ = (j >= 44); if (isQ) j -= 44;
    const float *Ap, *Bp; float* outp; int Nc, mt, nt;
    if (j < 32)      { mt=j>>4;      nt=j&15;     Ap=isQ?Z:g_HZ; Bp=isQ?X:g_HX; outp=isQ?g_Qzx:g_Pzx; Nc=N_DATA; }
    else if (j < 36) { mt=(j-32)>>1; nt=(j-32)&1; Ap=isQ?Z:g_HZ; Bp=isQ?Z:g_HZ; outp=isQ?g_Qzz:g_Pzz; Nc=M_IND; }
    else             { mt=(j-36)>>1; nt=(j-36)&1; Ap=isQ?T:g_HT; Bp=isQ?Z:g_HZ; outp=isQ?g_Qtz:g_Ptz; Nc=M_IND; }
    const int K = isQ ? D_IN : H_DIM;
    const int bm = mt*64, bn = nt*64;
    const int lrow = tid >> 1, lk = (tid & 1) << 3;
    const int tx = tid & 15, ty = tid >> 4;
    float acc[8][4] = {};
    for (int k0 = 0; k0 < K; k0 += 16) {
        float4 a0 = *(const float4*)&Ap[(bm+lrow)*K + k0 + lk];
        float4 a1 = *(const float4*)&Ap[(bm+lrow)*K + k0 + lk + 4];
        float4 b0 = *(const float4*)&Bp[(bn+lrow)*K + k0 + lk];
        float4 b1 = *(const float4*)&Bp[(bn+lrow)*K + k0 + lk + 4];
        __syncthreads();
        As[lk+0][lrow]=a0.x; As[lk+1][lrow]=a0.y; As[lk+2][lrow]=a0.z; As[lk+3][lrow]=a0.w;
        As[lk+4][lrow]=a1.x; As[lk+5][lrow]=a1.y; As[lk+6][lrow]=a1.z; As[lk+7][lrow]=a1.w;
        Bs[lk+0][lrow]=b0.x; Bs[lk+1][lrow]=b0.y; Bs[lk+2][lrow]=b0.z; Bs[lk+3][lrow]=b0.w;
        Bs[lk+4][lrow]=b1.x; Bs[lk+5][lrow]=b1.y; Bs[lk+6][lrow]=b1.z; Bs[lk+7][lrow]=b1.w;
        __syncthreads();
        #pragma unroll
        for (int kk = 0; kk < 16; ++kk) {
            float4 a4 = *(const float4*)&As[kk][ty*8];
            float4 a5 = *(const float4*)&As[kk][ty*8+4];
            float4 b4 = *(const float4*)&Bs[kk][tx*4];
            float a[8] = {a4.x,a4.y,a4.z,a4.w,a5.x,a5.y,a5.z,a5.w};
            float b[4] = {b4.x,b4.y,b4.z,b4.w};
            #pragma unroll
            for (int u = 0; u < 8; ++u)
                #pragma unroll
                for (int v = 0; v < 4; ++v) acc[u][v] = fmaf(a[u], b[v], acc[u][v]);
        }
    }
    const int n0 = bn + tx*4;
    #pragma unroll
    for (int u = 0; u < 8; ++u) {
        int m = bm + ty*8 + u;
        float4 o4 = {acc[u][0]+1.f, acc[u][1]+1.f, acc[u][2]+1.f, acc[u][3]+1.f};
        *(float4*)&outp[(size_t)m*Nc + n0] = o4;
    }
}

// =============== all 30 K matrices in one launch (440 jobs), FFMA2 inner ===============
__global__ void kbuild_all(const float* __restrict__ W2) {
    __shared__ __align__(16) float As[16][68];
    __shared__ __align__(16) float Bs[16][68];
    __shared__ float ws[H_DIM];
    const int tid = threadIdx.x;
    const int j = blockIdx.x;
    const float *Sa, *Sb, *Pp, *Qp; float* Kout; int Nc, mt, nt, i, jit;
    if (j < 320)      { i=j>>5; int r=j&31; mt=r>>4; nt=r&15; Sa=g_SZ; Sb=g_SX; Pp=g_Pzx; Qp=g_Qzx; Kout=g_Kzx+(size_t)i*M_IND*N_DATA; Nc=N_DATA; jit=0; }
    else if (j < 360) { i=(j-320)>>2; int r=(j-320)&3; mt=r>>1; nt=r&1; Sa=g_SZ; Sb=g_SZ; Pp=g_Pzz; Qp=g_Qzz; Kout=g_Kzz+(size_t)i*M_IND*M_IND; Nc=M_IND; jit=1; }
    else              { i=(j-360)>>3; int r=(j-360)&7; mt=r>>1; nt=r&1; Sa=g_ST; Sb=g_SZ; Pp=g_Ptz; Qp=g_Qtz; Kout=g_Ktz+(size_t)i*NT_PTS*M_IND; Nc=M_IND; jit=0; }
    for (int k = tid; k < H_DIM; k += 128) { float w = W2[k*C_OUT + i]; ws[k] = w*w; }
    const int bm = mt*64, bn = nt*64;
    const int lrow = tid >> 1, lk = (tid & 1) << 3;
    const int tx = tid & 15, ty = tid >> 4;
    ull accp[4][4] = {};
    for (int k0 = 0; k0 < H_DIM; k0 += 16) {
        float4 a0 = *(const float4*)&Sa[(bm+lrow)*H_DIM + k0 + lk];
        float4 a1 = *(const float4*)&Sa[(bm+lrow)*H_DIM + k0 + lk + 4];
        float4 b0 = *(const float4*)&Sb[(bn+lrow)*H_DIM + k0 + lk];
        float4 b1 = *(const float4*)&Sb[(bn+lrow)*H_DIM + k0 + lk + 4];
        __syncthreads();
        As[lk+0][lrow]=a0.x*ws[k0+lk+0]; As[lk+1][lrow]=a0.y*ws[k0+lk+1];
        As[lk+2][lrow]=a0.z*ws[k0+lk+2]; As[lk+3][lrow]=a0.w*ws[k0+lk+3];
        As[lk+4][lrow]=a1.x*ws[k0+lk+4]; As[lk+5][lrow]=a1.y*ws[k0+lk+5];
        As[lk+6][lrow]=a1.z*ws[k0+lk+6]; As[lk+7][lrow]=a1.w*ws[k0+lk+7];
        Bs[lk+0][lrow]=b0.x; Bs[lk+1][lrow]=b0.y; Bs[lk+2][lrow]=b0.z; Bs[lk+3][lrow]=b0.w;
        Bs[lk+4][lrow]=b1.x; Bs[lk+5][lrow]=b1.y; Bs[lk+6][lrow]=b1.z; Bs[lk+7][lrow]=b1.w;
        __syncthreads();
        #pragma unroll
        for (int kk = 0; kk < 16; ++kk) {
            ull ap[4];
            ap[0] = *(const ull*)&As[kk][ty*8 + 0];
            ap[1] = *(const ull*)&As[kk][ty*8 + 2];
            ap[2] = *(const ull*)&As[kk][ty*8 + 4];
            ap[3] = *(const ull*)&As[kk][ty*8 + 6];
            float4 b4 = *(const float4*)&Bs[kk][tx*4];
            ull db[4] = {dup2(b4.x), dup2(b4.y), dup2(b4.z), dup2(b4.w)};
            #pragma unroll
            for (int p = 0; p < 4; ++p)
                #pragma unroll
                for (int v = 0; v < 4; ++v) fma2(accp[p][v], ap[p], db[v]);
        }
    }
    const int n0 = bn + tx*4;
    #pragma unroll
    for (int p = 0; p < 4; ++p) {
        float2 c0 = unp(accp[p][0]);
        float2 c1 = unp(accp[p][1]);
        float2 c2 = unp(accp[p][2]);
        float2 c3 = unp(accp[p][3]);
        #pragma unroll
        for (int h = 0; h < 2; ++h) {
            int m = bm + ty*8 + 2*p + h;
            float u0 = h ? c0.y : c0.x;
            float u1 = h ? c1.y : c1.x;
            float u2 = h ? c2.y : c2.x;
            float u3 = h ? c3.y : c3.x;
            float4 p4 = *(const float4*)&Pp[(size_t)m*Nc + n0];
            float4 q4 = *(const float4*)&Qp[(size_t)m*Nc + n0];
            float4 o4;
            o4.x = SCALE_K*(p4.x + q4.x*u0);
            o4.y = SCALE_K*(p4.y + q4.y*u1);
            o4.z = SCALE_K*(p4.z + q4.z*u2);
            o4.w = SCALE_K*(p4.w + q4.w*u3);
            if (jit && m >= n0 && m < n0+4) {
                if (m == n0)   o4.x += JITTER_K;
                if (m == n0+1) o4.y += JITTER_K;
                if (m == n0+2) o4.z += JITTER_K;
                if (m == n0+3) o4.w += JITTER_K;
            }
            *(float4*)&Kout[(size_t)m*Nc + n0] = o4;
        }
    }
}

// =============== Bpart (split-K of 2*Kzx@Kzx^T) + alpha, FFMA2 inner ===============
__global__ void bgemm_alpha() {
    const int tid = threadIdx.x;
    const int j = blockIdx.x;
    if (j < 160) {
        __shared__ __align__(16) float As[16][68];
        __shared__ __align__(16) float Bs[16][68];
        int i = j >> 4, r = j & 15;
        int kc = r >> 2, mt = (r >> 1) & 1, nt = r & 1;
        const float* A = g_Kzx + (size_t)i*M_IND*N_DATA;
        const int bm = mt*64, bn = nt*64, kbeg = kc*256;
        const int lrow = tid >> 1, lk = (tid & 1) << 3;
        const int tx = tid & 15, ty = tid >> 4;
        ull accp[4][4] = {};
        for (int k0 = kbeg; k0 < kbeg+256; k0 += 16) {
            float4 a0 = *(const float4*)&A[(bm+lrow)*N_DATA + k0 + lk];
            float4 a1 = *(const float4*)&A[(bm+lrow)*N_DATA + k0 + lk + 4];
            float4 b0 = *(const float4*)&A[(bn+lrow)*N_DATA + k0 + lk];
            float4 b1 = *(const float4*)&A[(bn+lrow)*N_DATA + k0 + lk + 4];
            __syncthreads();
            As[lk+0][lrow]=a0.x; As[lk+1][lrow]=a0.y; As[lk+2][lrow]=a0.z; As[lk+3][lrow]=a0.w;
            As[lk+4][lrow]=a1.x; As[lk+5][lrow]=a1.y; As[lk+6][lrow]=a1.z; As[lk+7][lrow]=a1.w;
            Bs[lk+0][lrow]=b0.x; Bs[lk+1][lrow]=b0.y; Bs[lk+2][lrow]=b0.z; Bs[lk+3][lrow]=b0.w;
            Bs[lk+4][lrow]=b1.x; Bs[lk+5][lrow]=b1.y; Bs[lk+6][lrow]=b1.z; Bs[lk+7][lrow]=b1.w;
            __syncthreads();
            #pragma unroll
            for (int kk = 0; kk < 16; ++kk) {
                ull ap[4];
                ap[0] = *(const ull*)&As[kk][ty*8 + 0];
                ap[1] = *(const ull*)&As[kk][ty*8 + 2];
                ap[2] = *(const ull*)&As[kk][ty*8 + 4];
                ap[3] = *(const ull*)&As[kk][ty*8 + 6];
                float4 b4 = *(const float4*)&Bs[kk][tx*4];
                ull db[4] = {dup2(b4.x), dup2(b4.y), dup2(b4.z), dup2(b4.w)};
                #pragma unroll
                for (int p = 0; p < 4; ++p)
                    #pragma unroll
                    for (int v = 0; v < 4; ++v) fma2(accp[p][v], ap[p], db[v]);
            }
        }
        float* outp = g_Bpart + ((size_t)(kc*C_OUT + i)*M_IND)*M_IND;
        const int n0 = bn + tx*4;
        #pragma unroll
        for (int p = 0; p < 4; ++p) {
            float2 c0 = unp(accp[p][0]);
            float2 c1 = unp(accp[p][1]);
            float2 c2 = unp(accp[p][2]);
            float2 c3 = unp(accp[p][3]);
            int m = bm + ty*8 + 2*p;
            *(float4*)&outp[m*M_IND + n0] =
                make_float4(2.f*c0.x, 2.f*c1.x, 2.f*c2.x, 2.f*c3.x);
            *(float4*)&outp[(m+1)*M_IND + n0] =
                make_float4(2.f*c0.y, 2.f*c1.y, 2.f*c2.y, 2.f*c3.y);
        }
    } else {
        int k = j - 160;
        int i = k >> 2, rb = (k & 3) * 32;
        int w = tid >> 5, lane = tid & 31;
        #pragma unroll
        for (int rr = 0; rr < 8; ++rr) {
            int m = rb + w*8 + rr;
            const float* row = g_Kzx + ((size_t)i*M_IND + m)*N_DATA;
            float acc = 0.f;
            for (int n = lane; n < N_DATA; n += 32) acc += row[n] * g_LAM[n*C_OUT + i];
            #pragma unroll
            for (int o = 16; o; o >>= 1) acc += __shfl_down_sync(0xffffffffu, acc, o);
            if (lane == 0) g_alpha[i*M_IND + m] = acc;
        }
    }
}

// =============== register-tiled right-looking Cholesky (no spills) ===============
__global__ void __launch_bounds__(256) chol_all() {
    const int s = blockIdx.x, tid = threadIdx.x;
    const int isB = (s >= C_OUT);
    const int i = isB ? s - C_OUT : s;
    const float* A0 = g_Kzz + (size_t)i*M_IND*M_IND;
    const int tr = tid >> 4, tc = tid & 15;
    const int r0 = tr*8, c0 = tc*8;
    float a[8][8];
    #pragma unroll
    for (int u = 0; u < 8; ++u) {
        #pragma unroll
        for (int v = 0; v < 8; v += 4) {
            float4 x = *(const float4*)&A0[(r0+u)*M_IND + c0 + v];
            a[u][v]=x.x; a[u][v+1]=x.y; a[u][v+2]=x.z; a[u][v+3]=x.w;
            if (isB) {
                #pragma unroll
                for (int p = 0; p < 4; ++p) {
                    float4 y = *(const float4*)&g_Bpart[((size_t)(p*C_OUT+i)*M_IND + r0+u)*M_IND + c0+v];
                    a[u][v]+=y.x; a[u][v+1]+=y.y; a[u][v+2]+=y.z; a[u][v+3]+=y.w;
                }
            }
        }
    }
    __shared__ float colbuf[2][M_IND];
    for (int jb = 0; jb < 16; ++jb) {
        const bool owner = (tc == jb);
        #pragma unroll
        for (int v = 0; v < 8; ++v) {
            const int j = jb*8 + v;
            float* col = colbuf[v & 1];
            if (owner) {
                #pragma unroll
                for (int u = 0; u < 8; ++u) col[r0 + u] = a[u][v];
            }
            __syncthreads();
            const float djj = col[j];
            const float dinv = rsqrtf(djj);
            float ci[8], ck[8];
            #pragma unroll
            for (int u = 0; u < 8; ++u) {
                int ri = r0 + u;
                ci[u] = (ri > j) ? col[ri] * dinv : 0.f;
            }
            #pragma unroll
            for (int w = 0; w < 8; ++w) {
                int kk = c0 + w;
                ck[w] = (kk > j) ? col[kk] * dinv : 0.f;
            }
            if (owner) {
                #pragma unroll
                for (int u = 0; u < 8; ++u) {
                    int ri = r0 + u;
                    if (ri > j)       a[u][v] = ci[u];
                    else if (ri == j) a[u][v] = djj * dinv;
                }
            }
            #pragma unroll
            for (int u = 0; u < 8; ++u)
                #pragma unroll
                for (int w = 0; w < 8; ++w)
                    a[u][w] = fmaf(-ci[u], ck[w], a[u][w]);
        }
    }
    float* out = isB ? (g_LB + i*LPACK) : (g_LKzz + i*LPACK);
    if (c0 <= r0 + 7) {
        #pragma unroll
        for (int u = 0; u < 8; ++u) {
            int ri = r0 + u;
            if (ri >= c0) {
                int base = (ri*(ri+1)) >> 1;
                #pragma unroll
                for (int w = 0; w < 8; ++w) {
                    int kk = c0 + w;
                    if (kk <= ri) out[base + kk] = a[u][w];
                }
            }
        }
    }
}

// =============== solves: 160 fs blocks (4 solves/warp) + 10 meansolve ===============
__global__ void solve_all() {
    __shared__ float Lp[LPACK];
    __shared__ float dinv[M_IND];
    __shared__ float ysm[M_IND];
    const int b = blockIdx.x, tid = threadIdx.x;
    const int w = tid >> 5, lane = tid & 31;
    if (b < 160) {
        const int s = b >> 3;                 // 0..19
        const int t0 = (b & 7)*32 + w*4;      // base test index, 4 per warp
        const int i = (s < C_OUT) ? s : s - C_OUT;
        const float* Ls = (s < C_OUT) ? (g_LKzz + s*LPACK) : (g_LB + (s-C_OUT)*LPACK);
        for (int idx = tid; idx < LPACK; idx += 256) Lp[idx] = Ls[idx];
        if (tid < M_IND) dinv[tid] = 1.0f / Ls[((tid*(tid+1))>>1) + tid];
        __syncthreads();
        float br[4][4];   // [t][oreg]
        int base[4];
        #pragma unroll
        for (int r = 0; r < 4; ++r) {
            int row = r*32 + lane;
            base[r] = (row*(row+1)) >> 1;
        }
        #pragma unroll
        for (int tl = 0; tl < 4; ++tl) {
            const float* bvec = g_Ktz + ((size_t)i*NT_PTS + t0 + tl)*M_IND;
            #pragma unroll
            for (int r = 0; r < 4; ++r) br[tl][r] = bvec[lane + 32*r];
        }
        float ss[4] = {0.f, 0.f, 0.f, 0.f};
        #pragma unroll
        for (int oreg = 0; oreg < 4; ++oreg) {
            for (int jj = 0; jj < 32; ++jj) {
                int jc = oreg*32 + jj;
                float dv = dinv[jc];
                float Lv0 = Lp[base[oreg] + jc];      // shared across the 4 solves
                float Lv1 = (oreg < 3) ? Lp[base[oreg < 3 ? oreg+1 : 3] + jc] : 0.f;
                float Lv2 = (oreg < 2) ? Lp[base[oreg < 2 ? oreg+2 : 3] + jc] : 0.f;
                float Lv3 = (oreg < 1) ? Lp[base[3] + jc] : 0.f;
                #pragma unroll
                for (int tl = 0; tl < 4; ++tl) {
                    float yj = __shfl_sync(0xffffffffu, br[tl][oreg], jj) * dv;
                    ss[tl] = fmaf(yj, yj, ss[tl]);
                    if (lane > jj) br[tl][oreg] -= Lv0 * yj;
                    if (oreg < 3) br[tl][oreg+1 < 4 ? oreg+1 : 3] -= Lv1 * yj;
                    if (oreg < 2) br[tl][oreg+2 < 4 ? oreg+2 : 3] -= Lv2 * yj;
                    if (oreg < 1) br[tl][3] -= Lv3 * yj;
                }
            }
        }
        if (lane == 0) {
            #pragma unroll
            for (int tl = 0; tl < 4; ++tl) {
                if (s < C_OUT) g_SSZ[i*NT_PTS + t0 + tl] = ss[tl];
                else           g_SSB[i*NT_PTS + t0 + tl] = ss[tl];
            }
        }
    } else {
        const int i = b - 160;
        const float* Ls = g_LB + i*LPACK;
        for (int idx = tid; idx < LPACK; idx += 256) Lp[idx] = Ls[idx];
        if (tid < M_IND) dinv[tid] = 1.0f / Ls[((tid*(tid+1))>>1) + tid];
        __syncthreads();
        if (w != 0) return;
        float br[4]; int base[4];
        #pragma unroll
        for (int r = 0; r < 4; ++r) {
            br[r] = g_alpha[i*M_IND + lane + 32*r];
            int row = r*32 + lane;
            base[r] = (row*(row+1)) >> 1;
        }
        #pragma unroll
        for (int oreg = 0; oreg < 4; ++oreg) {
            for (int jj = 0; jj < 32; ++jj) {
                int jc = oreg*32 + jj;
                float yj = __shfl_sync(0xffffffffu, br[oreg], jj) * dinv[jc];
                if (lane == 0) ysm[jc] = yj;
                if (lane > jj) br[oreg] -= Lp[base[oreg] + jc] * yj;
                #pragma unroll
                for (int r = oreg+1; r < 4; ++r) br[r] -= Lp[base[r] + jc] * yj;
            }
        }
        __syncwarp();
        float xr[4];
        #pragma unroll
        for (int r = 0; r < 4; ++r) xr[r] = ysm[r*32 + lane];
        #pragma unroll
        for (int oreg = 3; oreg >= 0; --oreg) {
            for (int jj = 31; jj >= 0; --jj) {
                int jc = oreg*32 + jj;
                float xj = __shfl_sync(0xffffffffu, xr[oreg], jj) * dinv[jc];
                if (lane == 0) g_cvec[i*M_IND + jc] = xj;
                int rb2 = (jc*(jc+1)) >> 1;
                if (lane < jj) xr[oreg] -= Lp[rb2 + oreg*32 + lane] * xj;
                #pragma unroll
                for (int r = 0; r < 4; ++r)
                    if (r < oreg) xr[r] -= Lp[rb2 + r*32 + lane] * xj;
            }
        }
    }
}

// =============== epilogue: mean + variance ===============
__global__ void epilogue(const float* __restrict__ Xt, const float* __restrict__ W2,
                         float* __restrict__ out) {
    const int gw = blockIdx.x*8 + (threadIdx.x >> 5);
    const int lane = threadIdx.x & 31;
    const int t = gw / C_OUT, i = gw - t*C_OUT;
    float accU = 0.f, ph = 0.f, qx = 0.f;
    for (int k = lane; k < H_DIM; k += 32) {
        float s = g_ST[t*H_DIM + k];
        float h = g_HT[t*H_DIM + k];
        float w = W2[k*C_OUT + i];
        accU = fmaf(s*s, w*w, accU);
        ph = fmaf(h, h, ph);
    }
    for (int k = lane; k < D_IN; k += 32) { float x = Xt[t*D_IN + k]; qx = fmaf(x, x, qx); }
    float mean = 0.f;
    const float* kr = g_Ktz + ((size_t)i*NT_PTS + t)*M_IND;
    const float* cr = g_cvec + i*M_IND;
    #pragma unroll
    for (int r = 0; r < 4; ++r) mean += kr[lane + 32*r] * cr[lane + 32*r];
    #pragma unroll
    for (int o = 16; o; o >>= 1) {
        accU += __shfl_xor_sync(0xffffffffu, accU, o);
        ph   += __shfl_xor_sync(0xffffffffu, ph, o);
        qx   += __shfl_xor_sync(0xffffffffu, qx, o);
        mean += __shfl_xor_sync(0xffffffffu, mean, o);
    }
    if (lane == 0) {
        float kttd = SCALE_K * ((ph + 1.f) + (qx + 1.f)*accU);
        out[t*C_OUT + i] = mean;
        out[NT_PTS*C_OUT + t*C_OUT + i] = kttd - g_SSZ[i*NT_PTS + t] + g_SSB[i*NT_PTS + t];
    }
}

extern "C" void kernel_launch(void* const* d_in, const int* in_sizes, int n_in,
                              void* d_out, int out_size) {
    const float* X  = (const float*)d_in[0];
    const float* Y  = (const float*)d_in[1];
    const float* Z  = (const float*)d_in[2];
    const float* Xt = (const float*)d_in[3];
    const float* W1 = (const float*)d_in[4];
    const float* b1 = (const float*)d_in[5];
    const float* W2 = (const float*)d_in[6];
    const float* b2 = (const float*)d_in[7];
    float* out = (float*)d_out;

    fwd_all<<<dim3(6,22), 128>>>(X, Z, Xt, W1, b1);
    lam_kernel<<<128, 256>>>(Y, W2, b2);
    pq_all<<<88, 128>>>(X, Z, Xt);
    kbuild_all<<<440, 128>>>(W2);
    bgemm_alpha<<<200, 128>>>();
    chol_all<<<20, 256>>>();
    solve_all<<<170, 256>>>();
    epilogue<<<320, 256>>>(Xt, W2, out);
}

// round 12
// speedup vs baseline: 1.1393x; 1.0238x over previous
#include <cuda_runtime.h>

#define N_DATA 1024
#define D_IN   256
#define H_DIM  384
#define C_OUT  10
#define M_IND  128
#define NT_PTS 256
#define SCALE_K (1.0f/1024.0f)
#define JITTER_K 1e-3f
#define LPACK (M_IND*(M_IND+1)/2)

typedef unsigned long long ull;

// ---------------- device scratch ----------------
__device__ float g_HX[N_DATA*H_DIM];
__device__ float g_SX[N_DATA*H_DIM];
__device__ float g_HZ[M_IND*H_DIM];
__device__ float g_SZ[M_IND*H_DIM];
__device__ float g_HT[NT_PTS*H_DIM];
__device__ float g_ST[NT_PTS*H_DIM];
__device__ float g_LAM[N_DATA*C_OUT];
__device__ float g_Pzx[M_IND*N_DATA];
__device__ float g_Qzx[M_IND*N_DATA];
__device__ float g_Pzz[M_IND*M_IND];
__device__ float g_Qzz[M_IND*M_IND];
__device__ float g_Ptz[NT_PTS*M_IND];
__device__ float g_Qtz[NT_PTS*M_IND];
__device__ float g_Kzx[C_OUT*M_IND*N_DATA];
__device__ float g_Kzz[C_OUT*M_IND*M_IND];
__device__ float g_Ktz[C_OUT*NT_PTS*M_IND];
__device__ float g_Bpart[4*C_OUT*M_IND*M_IND];
__device__ float g_LKzz[C_OUT*LPACK];
__device__ float g_LB[C_OUT*LPACK];
__device__ float g_alpha[C_OUT*M_IND];
__device__ float g_cvec[C_OUT*M_IND];
__device__ float g_SSZ[C_OUT*NT_PTS];
__device__ float g_SSB[C_OUT*NT_PTS];

// ---------------- f32x2 packed helpers ----------------
__device__ __forceinline__ ull dup2(float x) {
    ull r; unsigned u = __float_as_uint(x);
    asm("mov.b64 %0, {%1, %1};" : "=l"(r) : "r"(u));
    return r;
}
__device__ __forceinline__ void fma2(ull& d, ull a, ull b) {
    asm("fma.rn.f32x2 %0, %1, %2, %0;" : "+l"(d) : "l"(a), "l"(b));
}
__device__ __forceinline__ float2 unp(ull v) {
    float2 f;
    asm("mov.b64 {%0, %1}, %2;" : "=f"(f.x), "=f"(f.y) : "l"(v));
    return f;
}

// =============== forward: 32-row tiles, grid (6,44), 128 thr, 4x4/thread ===============
__global__ void fwd_all(const float* __restrict__ X, const float* __restrict__ Z,
                        const float* __restrict__ T, const float* __restrict__ W1,
                        const float* __restrict__ b1) {
    __shared__ __align__(16) float As[16][36];
    __shared__ __align__(16) float Bs[16][68];
    const int tid = threadIdx.x;
    const int rb = blockIdx.y, nb = blockIdx.x;
    const float* src; float* Hd; float* Sd; int row0;
    if (rb < 32)      { src = X; Hd = g_HX; Sd = g_SX; row0 = rb*32; }
    else if (rb < 36) { src = Z; Hd = g_HZ; Sd = g_SZ; row0 = (rb-32)*32; }
    else              { src = T; Hd = g_HT; Sd = g_ST; row0 = (rb-36)*32; }
    const int arow = tid >> 2, aq = (tid & 3) << 2;
    const int kr = tid >> 3, nq = (tid & 7) << 3;
    const int tx = tid & 15, ty = tid >> 4;
    float acc[4][4] = {};
    for (int k0 = 0; k0 < D_IN; k0 += 16) {
        float4 av = *(const float4*)&src[(row0+arow)*D_IN + k0 + aq];
        float4 b0 = *(const float4*)&W1[(k0+kr)*H_DIM + nb*64 + nq];
        float4 b1v= *(const float4*)&W1[(k0+kr)*H_DIM + nb*64 + nq + 4];
        __syncthreads();
        As[aq+0][arow]=av.x; As[aq+1][arow]=av.y; As[aq+2][arow]=av.z; As[aq+3][arow]=av.w;
        *(float4*)&Bs[kr][nq] = b0; *(float4*)&Bs[kr][nq+4] = b1v;
        __syncthreads();
        #pragma unroll
        for (int kk = 0; kk < 16; ++kk) {
            float4 a4 = *(const float4*)&As[kk][ty*4];
            float4 b4 = *(const float4*)&Bs[kk][tx*4];
            float a[4] = {a4.x,a4.y,a4.z,a4.w};
            float b[4] = {b4.x,b4.y,b4.z,b4.w};
            #pragma unroll
            for (int u = 0; u < 4; ++u)
                #pragma unroll
                for (int v = 0; v < 4; ++v) acc[u][v] = fmaf(a[u], b[v], acc[u][v]);
        }
    }
    const int n0 = nb*64 + tx*4;
    float4 bv = *(const float4*)&b1[n0];
    #pragma unroll
    for (int u = 0; u < 4; ++u) {
        int m = row0 + ty*4 + u;
        float4 h4, s4;
        h4.x = tanhf(acc[u][0]+bv.x); h4.y = tanhf(acc[u][1]+bv.y);
        h4.z = tanhf(acc[u][2]+bv.z); h4.w = tanhf(acc[u][3]+bv.w);
        s4.x = 1.f-h4.x*h4.x; s4.y = 1.f-h4.y*h4.y;
        s4.z = 1.f-h4.z*h4.z; s4.w = 1.f-h4.w*h4.w;
        *(float4*)&Hd[m*H_DIM + n0] = h4;
        *(float4*)&Sd[m*H_DIM + n0] = s4;
    }
}

// =============== lambda1 = F + Y ===============
__global__ void lam_kernel(const float* __restrict__ Y, const float* __restrict__ W2,
                           const float* __restrict__ b2) {
    int warp = threadIdx.x >> 5, lane = threadIdx.x & 31;
    int row = blockIdx.x * 8 + warp;
    float h[12];
    #pragma unroll
    for (int r = 0; r < 12; ++r) h[r] = g_HX[row*H_DIM + lane + r*32];
    #pragma unroll
    for (int c = 0; c < C_OUT; ++c) {
        float acc = 0.f;
        #pragma unroll
        for (int r = 0; r < 12; ++r) acc += h[r] * W2[(lane + r*32)*C_OUT + c];
        #pragma unroll
        for (int o = 16; o; o >>= 1) acc += __shfl_down_sync(0xffffffffu, acc, o);
        if (lane == 0) g_LAM[row*C_OUT + c] = acc + b2[c] + Y[row*C_OUT + c];
    }
}

// =============== P and Q grams: 32x64 tiles, 176 jobs ===============
__global__ void pq_all(const float* __restrict__ X, const float* __restrict__ Z,
                       const float* __restrict__ T) {
    __shared__ __align__(16) float As[16][36];
    __shared__ __align__(16) float Bs[16][68];
    const int tid = threadIdx.x;
    int j = blockIdx.x;
    const int isQ = (j >= 88); if (isQ) j -= 88;
    const float *Ap, *Bp; float* outp; int Nc, mt, nt;
    if (j < 64)      { mt=j>>4;      nt=j&15;     Ap=isQ?Z:g_HZ; Bp=isQ?X:g_HX; outp=isQ?g_Qzx:g_Pzx; Nc=N_DATA; }
    else if (j < 72) { int q=j-64; mt=q>>1; nt=q&1; Ap=isQ?Z:g_HZ; Bp=isQ?Z:g_HZ; outp=isQ?g_Qzz:g_Pzz; Nc=M_IND; }
    else             { int q=j-72; mt=q>>1; nt=q&1; Ap=isQ?T:g_HT; Bp=isQ?Z:g_HZ; outp=isQ?g_Qtz:g_Ptz; Nc=M_IND; }
    const int K = isQ ? D_IN : H_DIM;
    const int bm = mt*32, bn = nt*64;
    const int arow = tid >> 2, aq = (tid & 3) << 2;
    const int lrow = tid >> 1, lk = (tid & 1) << 3;
    const int tx = tid & 15, ty = tid >> 4;
    float acc[4][4] = {};
    for (int k0 = 0; k0 < K; k0 += 16) {
        float4 av = *(const float4*)&Ap[(bm+arow)*K + k0 + aq];
        float4 b0 = *(const float4*)&Bp[(bn+lrow)*K + k0 + lk];
        float4 b1 = *(const float4*)&Bp[(bn+lrow)*K + k0 + lk + 4];
        __syncthreads();
        As[aq+0][arow]=av.x; As[aq+1][arow]=av.y; As[aq+2][arow]=av.z; As[aq+3][arow]=av.w;
        Bs[lk+0][lrow]=b0.x; Bs[lk+1][lrow]=b0.y; Bs[lk+2][lrow]=b0.z; Bs[lk+3][lrow]=b0.w;
        Bs[lk+4][lrow]=b1.x; Bs[lk+5][lrow]=b1.y; Bs[lk+6][lrow]=b1.z; Bs[lk+7][lrow]=b1.w;
        __syncthreads();
        #pragma unroll
        for (int kk = 0; kk < 16; ++kk) {
            float4 a4 = *(const float4*)&As[kk][ty*4];
            float4 b4 = *(const float4*)&Bs[kk][tx*4];
            float a[4] = {a4.x,a4.y,a4.z,a4.w};
            float b[4] = {b4.x,b4.y,b4.z,b4.w};
            #pragma unroll
            for (int u = 0; u < 4; ++u)
                #pragma unroll
                for (int v = 0; v < 4; ++v) acc[u][v] = fmaf(a[u], b[v], acc[u][v]);
        }
    }
    const int n0 = bn + tx*4;
    #pragma unroll
    for (int u = 0; u < 4; ++u) {
        int m = bm + ty*4 + u;
        float4 o4 = {acc[u][0]+1.f, acc[u][1]+1.f, acc[u][2]+1.f, acc[u][3]+1.f};
        *(float4*)&outp[(size_t)m*Nc + n0] = o4;
    }
}

// =============== all 30 K matrices in one launch (440 jobs), FFMA2 inner ===============
__global__ void kbuild_all(const float* __restrict__ W2) {
    __shared__ __align__(16) float As[16][68];
    __shared__ __align__(16) float Bs[16][68];
    __shared__ float ws[H_DIM];
    const int tid = threadIdx.x;
    const int j = blockIdx.x;
    const float *Sa, *Sb, *Pp, *Qp; float* Kout; int Nc, mt, nt, i, jit;
    if (j < 320)      { i=j>>5; int r=j&31; mt=r>>4; nt=r&15; Sa=g_SZ; Sb=g_SX; Pp=g_Pzx; Qp=g_Qzx; Kout=g_Kzx+(size_t)i*M_IND*N_DATA; Nc=N_DATA; jit=0; }
    else if (j < 360) { i=(j-320)>>2; int r=(j-320)&3; mt=r>>1; nt=r&1; Sa=g_SZ; Sb=g_SZ; Pp=g_Pzz; Qp=g_Qzz; Kout=g_Kzz+(size_t)i*M_IND*M_IND; Nc=M_IND; jit=1; }
    else              { i=(j-360)>>3; int r=(j-360)&7; mt=r>>1; nt=r&1; Sa=g_ST; Sb=g_SZ; Pp=g_Ptz; Qp=g_Qtz; Kout=g_Ktz+(size_t)i*NT_PTS*M_IND; Nc=M_IND; jit=0; }
    for (int k = tid; k < H_DIM; k += 128) { float w = W2[k*C_OUT + i]; ws[k] = w*w; }
    const int bm = mt*64, bn = nt*64;
    const int lrow = tid >> 1, lk = (tid & 1) << 3;
    const int tx = tid & 15, ty = tid >> 4;
    ull accp[4][4] = {};
    for (int k0 = 0; k0 < H_DIM; k0 += 16) {
        float4 a0 = *(const float4*)&Sa[(bm+lrow)*H_DIM + k0 + lk];
        float4 a1 = *(const float4*)&Sa[(bm+lrow)*H_DIM + k0 + lk + 4];
        float4 b0 = *(const float4*)&Sb[(bn+lrow)*H_DIM + k0 + lk];
        float4 b1 = *(const float4*)&Sb[(bn+lrow)*H_DIM + k0 + lk + 4];
        __syncthreads();
        As[lk+0][lrow]=a0.x*ws[k0+lk+0]; As[lk+1][lrow]=a0.y*ws[k0+lk+1];
        As[lk+2][lrow]=a0.z*ws[k0+lk+2]; As[lk+3][lrow]=a0.w*ws[k0+lk+3];
        As[lk+4][lrow]=a1.x*ws[k0+lk+4]; As[lk+5][lrow]=a1.y*ws[k0+lk+5];
        As[lk+6][lrow]=a1.z*ws[k0+lk+6]; As[lk+7][lrow]=a1.w*ws[k0+lk+7];
        Bs[lk+0][lrow]=b0.x; Bs[lk+1][lrow]=b0.y; Bs[lk+2][lrow]=b0.z; Bs[lk+3][lrow]=b0.w;
        Bs[lk+4][lrow]=b1.x; Bs[lk+5][lrow]=b1.y; Bs[lk+6][lrow]=b1.z; Bs[lk+7][lrow]=b1.w;
        __syncthreads();
        #pragma unroll
        for (int kk = 0; kk < 16; ++kk) {
            ull ap[4];
            ap[0] = *(const ull*)&As[kk][ty*8 + 0];
            ap[1] = *(const ull*)&As[kk][ty*8 + 2];
            ap[2] = *(const ull*)&As[kk][ty*8 + 4];
            ap[3] = *(const ull*)&As[kk][ty*8 + 6];
            float4 b4 = *(const float4*)&Bs[kk][tx*4];
            ull db[4] = {dup2(b4.x), dup2(b4.y), dup2(b4.z), dup2(b4.w)};
            #pragma unroll
            for (int p = 0; p < 4; ++p)
                #pragma unroll
                for (int v = 0; v < 4; ++v) fma2(accp[p][v], ap[p], db[v]);
        }
    }
    const int n0 = bn + tx*4;
    #pragma unroll
    for (int p = 0; p < 4; ++p) {
        float2 c0 = unp(accp[p][0]);
        float2 c1 = unp(accp[p][1]);
        float2 c2 = unp(accp[p][2]);
        float2 c3 = unp(accp[p][3]);
        #pragma unroll
        for (int h = 0; h < 2; ++h) {
            int m = bm + ty*8 + 2*p + h;
            float u0 = h ? c0.y : c0.x;
            float u1 = h ? c1.y : c1.x;
            float u2 = h ? c2.y : c2.x;
            float u3 = h ? c3.y : c3.x;
            float4 p4 = *(const float4*)&Pp[(size_t)m*Nc + n0];
            float4 q4 = *(const float4*)&Qp[(size_t)m*Nc + n0];
            float4 o4;
            o4.x = SCALE_K*(p4.x + q4.x*u0);
            o4.y = SCALE_K*(p4.y + q4.y*u1);
            o4.z = SCALE_K*(p4.z + q4.z*u2);
            o4.w = SCALE_K*(p4.w + q4.w*u3);
            if (jit && m >= n0 && m < n0+4) {
                if (m == n0)   o4.x += JITTER_K;
                if (m == n0+1) o4.y += JITTER_K;
                if (m == n0+2) o4.z += JITTER_K;
                if (m == n0+3) o4.w += JITTER_K;
            }
            *(float4*)&Kout[(size_t)m*Nc + n0] = o4;
        }
    }
}

// =============== Bpart symmetric (3 tiles/i, 120 blocks) + alpha (40) ===============
__global__ void bgemm_alpha() {
    const int tid = threadIdx.x;
    const int j = blockIdx.x;
    if (j < 120) {
        __shared__ __align__(16) float As[16][68];
        __shared__ __align__(16) float Bs[16][68];
        const int i = j / 12, r = j - i*12;
        const int tt = r % 3, kc = r / 3;
        const int mt = (tt == 2) ? 1 : 0;
        const int nt = (tt == 0) ? 0 : 1;
        const float* A = g_Kzx + (size_t)i*M_IND*N_DATA;
        const int bm = mt*64, bn = nt*64, kbeg = kc*256;
        const int lrow = tid >> 1, lk = (tid & 1) << 3;
        const int tx = tid & 15, ty = tid >> 4;
        ull accp[4][4] = {};
        for (int k0 = kbeg; k0 < kbeg+256; k0 += 16) {
            float4 a0 = *(const float4*)&A[(bm+lrow)*N_DATA + k0 + lk];
            float4 a1 = *(const float4*)&A[(bm+lrow)*N_DATA + k0 + lk + 4];
            float4 b0 = *(const float4*)&A[(bn+lrow)*N_DATA + k0 + lk];
            float4 b1 = *(const float4*)&A[(bn+lrow)*N_DATA + k0 + lk + 4];
            __syncthreads();
            As[lk+0][lrow]=a0.x; As[lk+1][lrow]=a0.y; As[lk+2][lrow]=a0.z; As[lk+3][lrow]=a0.w;
            As[lk+4][lrow]=a1.x; As[lk+5][lrow]=a1.y; As[lk+6][lrow]=a1.z; As[lk+7][lrow]=a1.w;
            Bs[lk+0][lrow]=b0.x; Bs[lk+1][lrow]=b0.y; Bs[lk+2][lrow]=b0.z; Bs[lk+3][lrow]=b0.w;
            Bs[lk+4][lrow]=b1.x; Bs[lk+5][lrow]=b1.y; Bs[lk+6][lrow]=b1.z; Bs[lk+7][lrow]=b1.w;
            __syncthreads();
            #pragma unroll
            for (int kk = 0; kk < 16; ++kk) {
                ull ap[4];
                ap[0] = *(const ull*)&As[kk][ty*8 + 0];
                ap[1] = *(const ull*)&As[kk][ty*8 + 2];
                ap[2] = *(const ull*)&As[kk][ty*8 + 4];
                ap[3] = *(const ull*)&As[kk][ty*8 + 6];
                float4 b4 = *(const float4*)&Bs[kk][tx*4];
                ull db[4] = {dup2(b4.x), dup2(b4.y), dup2(b4.z), dup2(b4.w)};
                #pragma unroll
                for (int p = 0; p < 4; ++p)
                    #pragma unroll
                    for (int v = 0; v < 4; ++v) fma2(accp[p][v], ap[p], db[v]);
            }
        }
        float* outp = g_Bpart + ((size_t)(kc*C_OUT + i)*M_IND)*M_IND;
        const int n0 = bn + tx*4;
        #pragma unroll
        for (int p = 0; p < 4; ++p) {
            float2 cc[4];
            cc[0] = unp(accp[p][0]); cc[1] = unp(accp[p][1]);
            cc[2] = unp(accp[p][2]); cc[3] = unp(accp[p][3]);
            int m = bm + ty*8 + 2*p;
            *(float4*)&outp[m*M_IND + n0] =
                make_float4(2.f*cc[0].x, 2.f*cc[1].x, 2.f*cc[2].x, 2.f*cc[3].x);
            *(float4*)&outp[(m+1)*M_IND + n0] =
                make_float4(2.f*cc[0].y, 2.f*cc[1].y, 2.f*cc[2].y, 2.f*cc[3].y);
            if (tt == 1) {   // mirror into the (1,0) tile
                #pragma unroll
                for (int v = 0; v < 4; ++v) {
                    outp[(n0+v)*M_IND + m]   = 2.f*cc[v].x;
                    outp[(n0+v)*M_IND + m+1] = 2.f*cc[v].y;
                }
            }
        }
    } else {
        int k = j - 120;
        int i = k >> 2, rb = (k & 3) * 32;
        int w = tid >> 5, lane = tid & 31;
        #pragma unroll
        for (int rr = 0; rr < 8; ++rr) {
            int m = rb + w*8 + rr;
            const float* row = g_Kzx + ((size_t)i*M_IND + m)*N_DATA;
            float acc = 0.f;
            for (int n = lane; n < N_DATA; n += 32) acc += row[n] * g_LAM[n*C_OUT + i];
            #pragma unroll
            for (int o = 16; o; o >>= 1) acc += __shfl_down_sync(0xffffffffu, acc, o);
            if (lane == 0) g_alpha[i*M_IND + m] = acc;
        }
    }
}

// =============== register-tiled right-looking Cholesky (no spills) ===============
__global__ void __launch_bounds__(256) chol_all() {
    const int s = blockIdx.x, tid = threadIdx.x;
    const int isB = (s >= C_OUT);
    const int i = isB ? s - C_OUT : s;
    const float* A0 = g_Kzz + (size_t)i*M_IND*M_IND;
    const int tr = tid >> 4, tc = tid & 15;
    const int r0 = tr*8, c0 = tc*8;
    float a[8][8];
    #pragma unroll
    for (int u = 0; u < 8; ++u) {
        #pragma unroll
        for (int v = 0; v < 8; v += 4) {
            float4 x = *(const float4*)&A0[(r0+u)*M_IND + c0 + v];
            a[u][v]=x.x; a[u][v+1]=x.y; a[u][v+2]=x.z; a[u][v+3]=x.w;
            if (isB) {
                #pragma unroll
                for (int p = 0; p < 4; ++p) {
                    float4 y = *(const float4*)&g_Bpart[((size_t)(p*C_OUT+i)*M_IND + r0+u)*M_IND + c0+v];
                    a[u][v]+=y.x; a[u][v+1]+=y.y; a[u][v+2]+=y.z; a[u][v+3]+=y.w;
                }
            }
        }
    }
    __shared__ float colbuf[2][M_IND];
    for (int jb = 0; jb < 16; ++jb) {
        const bool owner = (tc == jb);
        #pragma unroll
        for (int v = 0; v < 8; ++v) {
            const int j = jb*8 + v;
            float* col = colbuf[v & 1];
            if (owner) {
                #pragma unroll
                for (int u = 0; u < 8; ++u) col[r0 + u] = a[u][v];
            }
            __syncthreads();
            const float djj = col[j];
            const float dinv = rsqrtf(djj);
            float ci[8], ck[8];
            #pragma unroll
            for (int u = 0; u < 8; ++u) {
                int ri = r0 + u;
                ci[u] = (ri > j) ? col[ri] * dinv : 0.f;
            }
            #pragma unroll
            for (int w = 0; w < 8; ++w) {
                int kk = c0 + w;
                ck[w] = (kk > j) ? col[kk] * dinv : 0.f;
            }
            if (owner) {
                #pragma unroll
                for (int u = 0; u < 8; ++u) {
                    int ri = r0 + u;
                    if (ri > j)       a[u][v] = ci[u];
                    else if (ri == j) a[u][v] = djj * dinv;
                }
            }
            #pragma unroll
            for (int u = 0; u < 8; ++u)
                #pragma unroll
                for (int w = 0; w < 8; ++w)
                    a[u][w] = fmaf(-ci[u], ck[w], a[u][w]);
        }
    }
    float* out = isB ? (g_LB + i*LPACK) : (g_LKzz + i*LPACK);
    if (c0 <= r0 + 7) {
        #pragma unroll
        for (int u = 0; u < 8; ++u) {
            int ri = r0 + u;
            if (ri >= c0) {
                int base = (ri*(ri+1)) >> 1;
                #pragma unroll
                for (int w = 0; w < 8; ++w) {
                    int kk = c0 + w;
                    if (kk <= ri) out[base + kk] = a[u][w];
                }
            }
        }
    }
}

// =============== solves: 160 fs blocks (4 solves/warp) + 10 meansolve ===============
__global__ void solve_all() {
    __shared__ float Lp[LPACK];
    __shared__ float dinv[M_IND];
    __shared__ float ysm[M_IND];
    const int b = blockIdx.x, tid = threadIdx.x;
    const int w = tid >> 5, lane = tid & 31;
    if (b < 160) {
        const int s = b >> 3;
        const int t0 = (b & 7)*32 + w*4;
        const int i = (s < C_OUT) ? s : s - C_OUT;
        const float* Ls = (s < C_OUT) ? (g_LKzz + s*LPACK) : (g_LB + (s-C_OUT)*LPACK);
        for (int idx = tid; idx < LPACK; idx += 256) Lp[idx] = Ls[idx];
        if (tid < M_IND) dinv[tid] = 1.0f / Ls[((tid*(tid+1))>>1) + tid];
        __syncthreads();
        float br[4][4];
        int base[4];
        #pragma unroll
        for (int r = 0; r < 4; ++r) {
            int row = r*32 + lane;
            base[r] = (row*(row+1)) >> 1;
        }
        #pragma unroll
        for (int tl = 0; tl < 4; ++tl) {
            const float* bvec = g_Ktz + ((size_t)i*NT_PTS + t0 + tl)*M_IND;
            #pragma unroll
            for (int r = 0; r < 4; ++r) br[tl][r] = bvec[lane + 32*r];
        }
        float ss[4] = {0.f, 0.f, 0.f, 0.f};
        #pragma unroll
        for (int oreg = 0; oreg < 4; ++oreg) {
            for (int jj = 0; jj < 32; ++jj) {
                int jc = oreg*32 + jj;
                float dv = dinv[jc];
                float Lv0 = Lp[base[oreg] + jc];
                float Lv1 = (oreg < 3) ? Lp[base[oreg < 3 ? oreg+1 : 3] + jc] : 0.f;
                float Lv2 = (oreg < 2) ? Lp[base[oreg < 2 ? oreg+2 : 3] + jc] : 0.f;
                float Lv3 = (oreg < 1) ? Lp[base[3] + jc] : 0.f;
                #pragma unroll
                for (int tl = 0; tl < 4; ++tl) {
                    float yj = __shfl_sync(0xffffffffu, br[tl][oreg], jj) * dv;
                    ss[tl] = fmaf(yj, yj, ss[tl]);
                    if (lane > jj) br[tl][oreg] -= Lv0 * yj;
                    if (oreg < 3) br[tl][oreg+1 < 4 ? oreg+1 : 3] -= Lv1 * yj;
                    if (oreg < 2) br[tl][oreg+2 < 4 ? oreg+2 : 3] -= Lv2 * yj;
                    if (oreg < 1) br[tl][3] -= Lv3 * yj;
                }
            }
        }
        if (lane == 0) {
            #pragma unroll
            for (int tl = 0; tl < 4; ++tl) {
                if (s < C_OUT) g_SSZ[i*NT_PTS + t0 + tl] = ss[tl];
                else           g_SSB[i*NT_PTS + t0 + tl] = ss[tl];
            }
        }
    } else {
        const int i = b - 160;
        const float* Ls = g_LB + i*LPACK;
        for (int idx = tid; idx < LPACK; idx += 256) Lp[idx] = Ls[idx];
        if (tid < M_IND) dinv[tid] = 1.0f / Ls[((tid*(tid+1))>>1) + tid];
        __syncthreads();
        if (w != 0) return;
        float br[4]; int base[4];
        #pragma unroll
        for (int r = 0; r < 4; ++r) {
            br[r] = g_alpha[i*M_IND + lane + 32*r];
            int row = r*32 + lane;
            base[r] = (row*(row+1)) >> 1;
        }
        #pragma unroll
        for (int oreg = 0; oreg < 4; ++oreg) {
            for (int jj = 0; jj < 32; ++jj) {
                int jc = oreg*32 + jj;
                float yj = __shfl_sync(0xffffffffu, br[oreg], jj) * dinv[jc];
                if (lane == 0) ysm[jc] = yj;
                if (lane > jj) br[oreg] -= Lp[base[oreg] + jc] * yj;
                #pragma unroll
                for (int r = oreg+1; r < 4; ++r) br[r] -= Lp[base[r] + jc] * yj;
            }
        }
        __syncwarp();
        float xr[4];
        #pragma unroll
        for (int r = 0; r < 4; ++r) xr[r] = ysm[r*32 + lane];
        #pragma unroll
        for (int oreg = 3; oreg >= 0; --oreg) {
            for (int jj = 31; jj >= 0; --jj) {
                int jc = oreg*32 + jj;
                float xj = __shfl_sync(0xffffffffu, xr[oreg], jj) * dinv[jc];
                if (lane == 0) g_cvec[i*M_IND + jc] = xj;
                int rb2 = (jc*(jc+1)) >> 1;
                if (lane < jj) xr[oreg] -= Lp[rb2 + oreg*32 + lane] * xj;
                #pragma unroll
                for (int r = 0; r < 4; ++r)
                    if (r < oreg) xr[r] -= Lp[rb2 + r*32 + lane] * xj;
            }
        }
    }
}

// =============== epilogue: mean + variance ===============
__global__ void epilogue(const float* __restrict__ Xt, const float* __restrict__ W2,
                         float* __restrict__ out) {
    const int gw = blockIdx.x*8 + (threadIdx.x >> 5);
    const int lane = threadIdx.x & 31;
    const int t = gw / C_OUT, i = gw - t*C_OUT;
    float accU = 0.f, ph = 0.f, qx = 0.f;
    for (int k = lane; k < H_DIM; k += 32) {
        float s = g_ST[t*H_DIM + k];
        float h = g_HT[t*H_DIM + k];
        float w = W2[k*C_OUT + i];
        accU = fmaf(s*s, w*w, accU);
        ph = fmaf(h, h, ph);
    }
    for (int k = lane; k < D_IN; k += 32) { float x = Xt[t*D_IN + k]; qx = fmaf(x, x, qx); }
    float mean = 0.f;
    const float* kr = g_Ktz + ((size_t)i*NT_PTS + t)*M_IND;
    const float* cr = g_cvec + i*M_IND;
    #pragma unroll
    for (int r = 0; r < 4; ++r) mean += kr[lane + 32*r] * cr[lane + 32*r];
    #pragma unroll
    for (int o = 16; o; o >>= 1) {
        accU += __shfl_xor_sync(0xffffffffu, accU, o);
        ph   += __shfl_xor_sync(0xffffffffu, ph, o);
        qx   += __shfl_xor_sync(0xffffffffu, qx, o);
        mean += __shfl_xor_sync(0xffffffffu, mean, o);
    }
    if (lane == 0) {
        float kttd = SCALE_K * ((ph + 1.f) + (qx + 1.f)*accU);
        out[t*C_OUT + i] = mean;
        out[NT_PTS*C_OUT + t*C_OUT + i] = kttd - g_SSZ[i*NT_PTS + t] + g_SSB[i*NT_PTS + t];
    }
}

extern "C" void kernel_launch(void* const* d_in, const int* in_sizes, int n_in,
                              void* d_out, int out_size) {
    const float* X  = (const float*)d_in[0];
    const float* Y  = (const float*)d_in[1];
    const float* Z  = (const float*)d_in[2];
    const float* Xt = (const float*)d_in[3];
    const float* W1 = (const float*)d_in[4];
    const float* b1 = (const float*)d_in[5];
    const float* W2 = (const float*)d_in[6];
    const float* b2 = (const float*)d_in[7];
    float* out = (float*)d_out;

    fwd_all<<<dim3(6,44), 128>>>(X, Z, Xt, W1, b1);
    lam_kernel<<<128, 256>>>(Y, W2, b2);
    pq_all<<<176, 128>>>(X, Z, Xt);
    kbuild_all<<<440, 128>>>(W2);
    bgemm_alpha<<<160, 128>>>();
    chol_all<<<20, 256>>>();
    solve_all<<<170, 256>>>();
    epilogue<<<320, 256>>>(Xt, W2, out);
}

// round 13
// speedup vs baseline: 1.1529x; 1.0119x over previous
#include <cuda_runtime.h>

#define N_DATA 1024
#define D_IN   256
#define H_DIM  384
#define C_OUT  10
#define M_IND  128
#define NT_PTS 256
#define SCALE_K (1.0f/1024.0f)
#define JITTER_K 1e-3f
#define LPACK (M_IND*(M_IND+1)/2)

typedef unsigned long long ull;

// ---------------- device scratch ----------------
__device__ float g_HX[N_DATA*H_DIM];
__device__ float g_SX[N_DATA*H_DIM];
__device__ float g_HZ[M_IND*H_DIM];
__device__ float g_SZ[M_IND*H_DIM];
__device__ float g_HT[NT_PTS*H_DIM];
__device__ float g_ST[NT_PTS*H_DIM];
__device__ float g_LAM[N_DATA*C_OUT];
__device__ float g_Pzx[M_IND*N_DATA];
__device__ float g_Qzx[M_IND*N_DATA];
__device__ float g_Pzz[M_IND*M_IND];
__device__ float g_Qzz[M_IND*M_IND];
__device__ float g_Ptz[NT_PTS*M_IND];
__device__ float g_Qtz[NT_PTS*M_IND];
__device__ float g_Uzx[2*C_OUT*M_IND*N_DATA];
__device__ float g_Uzz[2*C_OUT*M_IND*M_IND];
__device__ float g_Utz[2*C_OUT*NT_PTS*M_IND];
__device__ float g_Kzx[C_OUT*M_IND*N_DATA];
__device__ float g_Kzz[C_OUT*M_IND*M_IND];
__device__ float g_Ktz[C_OUT*NT_PTS*M_IND];
__device__ float g_Bpart[8*C_OUT*M_IND*M_IND];
__device__ float g_LKzz[C_OUT*LPACK];
__device__ float g_LB[C_OUT*LPACK];
__device__ float g_alpha[C_OUT*M_IND];
__device__ float g_cvec[C_OUT*M_IND];
__device__ float g_SSZ[C_OUT*NT_PTS];
__device__ float g_SSB[C_OUT*NT_PTS];

// ---------------- f32x2 packed helpers ----------------
__device__ __forceinline__ ull dup2(float x) {
    ull r; unsigned u = __float_as_uint(x);
    asm("mov.b64 %0, {%1, %1};" : "=l"(r) : "r"(u));
    return r;
}
__device__ __forceinline__ void fma2(ull& d, ull a, ull b) {
    asm("fma.rn.f32x2 %0, %1, %2, %0;" : "+l"(d) : "l"(a), "l"(b));
}
__device__ __forceinline__ float2 unp(ull v) {
    float2 f;
    asm("mov.b64 {%0, %1}, %2;" : "=f"(f.x), "=f"(f.y) : "l"(v));
    return f;
}

// =============== forward: 32-row tiles, grid (6,44), 128 thr, 4x4/thread ===============
__global__ void fwd_all(const float* __restrict__ X, const float* __restrict__ Z,
                        const float* __restrict__ T, const float* __restrict__ W1,
                        const float* __restrict__ b1) {
    __shared__ __align__(16) float As[16][36];
    __shared__ __align__(16) float Bs[16][68];
    const int tid = threadIdx.x;
    const int rb = blockIdx.y, nb = blockIdx.x;
    const float* src; float* Hd; float* Sd; int row0;
    if (rb < 32)      { src = X; Hd = g_HX; Sd = g_SX; row0 = rb*32; }
    else if (rb < 36) { src = Z; Hd = g_HZ; Sd = g_SZ; row0 = (rb-32)*32; }
    else              { src = T; Hd = g_HT; Sd = g_ST; row0 = (rb-36)*32; }
    const int arow = tid >> 2, aq = (tid & 3) << 2;
    const int kr = tid >> 3, nq = (tid & 7) << 3;
    const int tx = tid & 15, ty = tid >> 4;
    float acc[4][4] = {};
    for (int k0 = 0; k0 < D_IN; k0 += 16) {
        float4 av = *(const float4*)&src[(row0+arow)*D_IN + k0 + aq];
        float4 b0 = *(const float4*)&W1[(k0+kr)*H_DIM + nb*64 + nq];
        float4 b1v= *(const float4*)&W1[(k0+kr)*H_DIM + nb*64 + nq + 4];
        __syncthreads();
        As[aq+0][arow]=av.x; As[aq+1][arow]=av.y; As[aq+2][arow]=av.z; As[aq+3][arow]=av.w;
        *(float4*)&Bs[kr][nq] = b0; *(float4*)&Bs[kr][nq+4] = b1v;
        __syncthreads();
        #pragma unroll
        for (int kk = 0; kk < 16; ++kk) {
            float4 a4 = *(const float4*)&As[kk][ty*4];
            float4 b4 = *(const float4*)&Bs[kk][tx*4];
            float a[4] = {a4.x,a4.y,a4.z,a4.w};
            float b[4] = {b4.x,b4.y,b4.z,b4.w};
            #pragma unroll
            for (int u = 0; u < 4; ++u)
                #pragma unroll
                for (int v = 0; v < 4; ++v) acc[u][v] = fmaf(a[u], b[v], acc[u][v]);
        }
    }
    const int n0 = nb*64 + tx*4;
    float4 bv = *(const float4*)&b1[n0];
    #pragma unroll
    for (int u = 0; u < 4; ++u) {
        int m = row0 + ty*4 + u;
        float4 h4, s4;
        h4.x = tanhf(acc[u][0]+bv.x); h4.y = tanhf(acc[u][1]+bv.y);
        h4.z = tanhf(acc[u][2]+bv.z); h4.w = tanhf(acc[u][3]+bv.w);
        s4.x = 1.f-h4.x*h4.x; s4.y = 1.f-h4.y*h4.y;
        s4.z = 1.f-h4.z*h4.z; s4.w = 1.f-h4.w*h4.w;
        *(float4*)&Hd[m*H_DIM + n0] = h4;
        *(float4*)&Sd[m*H_DIM + n0] = s4;
    }
}

// =============== P/Q grams (blocks 0..175) + lambda (blocks 176..431) ===============
__global__ void pq_lam(const float* __restrict__ X, const float* __restrict__ Z,
                       const float* __restrict__ T, const float* __restrict__ Y,
                       const float* __restrict__ W2, const float* __restrict__ b2) {
    const int tid = threadIdx.x;
    if (blockIdx.x >= 176) {
        int warp = tid >> 5, lane = tid & 31;
        int row = (blockIdx.x - 176)*4 + warp;
        float h[12];
        #pragma unroll
        for (int r = 0; r < 12; ++r) h[r] = g_HX[row*H_DIM + lane + r*32];
        #pragma unroll
        for (int c = 0; c < C_OUT; ++c) {
            float acc = 0.f;
            #pragma unroll
            for (int r = 0; r < 12; ++r) acc += h[r] * W2[(lane + r*32)*C_OUT + c];
            #pragma unroll
            for (int o = 16; o; o >>= 1) acc += __shfl_down_sync(0xffffffffu, acc, o);
            if (lane == 0) g_LAM[row*C_OUT + c] = acc + b2[c] + Y[row*C_OUT + c];
        }
        return;
    }
    __shared__ __align__(16) float As[16][36];
    __shared__ __align__(16) float Bs[16][68];
    int j = blockIdx.x;
    const int isQ = (j >= 88); if (isQ) j -= 88;
    const float *Ap, *Bp; float* outp; int Nc, mt, nt;
    if (j < 64)      { mt=j>>4;      nt=j&15;     Ap=isQ?Z:g_HZ; Bp=isQ?X:g_HX; outp=isQ?g_Qzx:g_Pzx; Nc=N_DATA; }
    else if (j < 72) { int q=j-64; mt=q>>1; nt=q&1; Ap=isQ?Z:g_HZ; Bp=isQ?Z:g_HZ; outp=isQ?g_Qzz:g_Pzz; Nc=M_IND; }
    else             { int q=j-72; mt=q>>1; nt=q&1; Ap=isQ?T:g_HT; Bp=isQ?Z:g_HZ; outp=isQ?g_Qtz:g_Ptz; Nc=M_IND; }
    const int K = isQ ? D_IN : H_DIM;
    const int bm = mt*32, bn = nt*64;
    const int arow = tid >> 2, aq = (tid & 3) << 2;
    const int lrow = tid >> 1, lk = (tid & 1) << 3;
    const int tx = tid & 15, ty = tid >> 4;
    float acc[4][4] = {};
    for (int k0 = 0; k0 < K; k0 += 16) {
        float4 av = *(const float4*)&Ap[(bm+arow)*K + k0 + aq];
        float4 b0 = *(const float4*)&Bp[(bn+lrow)*K + k0 + lk];
        float4 b1 = *(const float4*)&Bp[(bn+lrow)*K + k0 + lk + 4];
        __syncthreads();
        As[aq+0][arow]=av.x; As[aq+1][arow]=av.y; As[aq+2][arow]=av.z; As[aq+3][arow]=av.w;
        Bs[lk+0][lrow]=b0.x; Bs[lk+1][lrow]=b0.y; Bs[lk+2][lrow]=b0.z; Bs[lk+3][lrow]=b0.w;
        Bs[lk+4][lrow]=b1.x; Bs[lk+5][lrow]=b1.y; Bs[lk+6][lrow]=b1.z; Bs[lk+7][lrow]=b1.w;
        __syncthreads();
        #pragma unroll
        for (int kk = 0; kk < 16; ++kk) {
            float4 a4 = *(const float4*)&As[kk][ty*4];
            float4 b4 = *(const float4*)&Bs[kk][tx*4];
            float a[4] = {a4.x,a4.y,a4.z,a4.w};
            float b[4] = {b4.x,b4.y,b4.z,b4.w};
            #pragma unroll
            for (int u = 0; u < 4; ++u)
                #pragma unroll
                for (int v = 0; v < 4; ++v) acc[u][v] = fmaf(a[u], b[v], acc[u][v]);
        }
    }
    const int n0 = bn + tx*4;
    #pragma unroll
    for (int u = 0; u < 4; ++u) {
        int m = bm + ty*4 + u;
        float4 o4 = {acc[u][0]+1.f, acc[u][1]+1.f, acc[u][2]+1.f, acc[u][3]+1.f};
        *(float4*)&outp[(size_t)m*Nc + n0] = o4;
    }
}

// =============== U partials: split-K=2, 880 blocks, FFMA2 inner ===============
__global__ void kbuild_all(const float* __restrict__ W2) {
    __shared__ __align__(16) float As[16][68];
    __shared__ __align__(16) float Bs[16][68];
    __shared__ float ws[H_DIM];
    const int tid = threadIdx.x;
    const int half = (blockIdx.x >= 440) ? 1 : 0;
    const int j = blockIdx.x - half*440;
    const float *Sa, *Sb; float* Uout; int Nc, mt, nt, i;
    if (j < 320)      { i=j>>5; int r=j&31; mt=r>>4; nt=r&15; Sa=g_SZ; Sb=g_SX;
                        Uout=g_Uzx + ((size_t)half*C_OUT + i)*M_IND*N_DATA; Nc=N_DATA; }
    else if (j < 360) { i=(j-320)>>2; int r=(j-320)&3; mt=r>>1; nt=r&1; Sa=g_SZ; Sb=g_SZ;
                        Uout=g_Uzz + ((size_t)half*C_OUT + i)*M_IND*M_IND; Nc=M_IND; }
    else              { i=(j-360)>>3; int r=(j-360)&7; mt=r>>1; nt=r&1; Sa=g_ST; Sb=g_SZ;
                        Uout=g_Utz + ((size_t)half*C_OUT + i)*NT_PTS*M_IND; Nc=M_IND; }
    for (int k = tid; k < H_DIM; k += 128) { float w = W2[k*C_OUT + i]; ws[k] = w*w; }
    const int bm = mt*64, bn = nt*64;
    const int lrow = tid >> 1, lk = (tid & 1) << 3;
    const int tx = tid & 15, ty = tid >> 4;
    const int kbeg = half*192, kend = kbeg + 192;
    ull accp[4][4] = {};
    for (int k0 = kbeg; k0 < kend; k0 += 16) {
        float4 a0 = *(const float4*)&Sa[(bm+lrow)*H_DIM + k0 + lk];
        float4 a1 = *(const float4*)&Sa[(bm+lrow)*H_DIM + k0 + lk + 4];
        float4 b0 = *(const float4*)&Sb[(bn+lrow)*H_DIM + k0 + lk];
        float4 b1 = *(const float4*)&Sb[(bn+lrow)*H_DIM + k0 + lk + 4];
        __syncthreads();
        As[lk+0][lrow]=a0.x*ws[k0+lk+0]; As[lk+1][lrow]=a0.y*ws[k0+lk+1];
        As[lk+2][lrow]=a0.z*ws[k0+lk+2]; As[lk+3][lrow]=a0.w*ws[k0+lk+3];
        As[lk+4][lrow]=a1.x*ws[k0+lk+4]; As[lk+5][lrow]=a1.y*ws[k0+lk+5];
        As[lk+6][lrow]=a1.z*ws[k0+lk+6]; As[lk+7][lrow]=a1.w*ws[k0+lk+7];
        Bs[lk+0][lrow]=b0.x; Bs[lk+1][lrow]=b0.y; Bs[lk+2][lrow]=b0.z; Bs[lk+3][lrow]=b0.w;
        Bs[lk+4][lrow]=b1.x; Bs[lk+5][lrow]=b1.y; Bs[lk+6][lrow]=b1.z; Bs[lk+7][lrow]=b1.w;
        __syncthreads();
        #pragma unroll
        for (int kk = 0; kk < 16; ++kk) {
            ull ap[4];
            ap[0] = *(const ull*)&As[kk][ty*8 + 0];
            ap[1] = *(const ull*)&As[kk][ty*8 + 2];
            ap[2] = *(const ull*)&As[kk][ty*8 + 4];
            ap[3] = *(const ull*)&As[kk][ty*8 + 6];
            float4 b4 = *(const float4*)&Bs[kk][tx*4];
            ull db[4] = {dup2(b4.x), dup2(b4.y), dup2(b4.z), dup2(b4.w)};
            #pragma unroll
            for (int p = 0; p < 4; ++p)
                #pragma unroll
                for (int v = 0; v < 4; ++v) fma2(accp[p][v], ap[p], db[v]);
        }
    }
    const int n0 = bn + tx*4;
    #pragma unroll
    for (int p = 0; p < 4; ++p) {
        float2 c0 = unp(accp[p][0]);
        float2 c1 = unp(accp[p][1]);
        float2 c2 = unp(accp[p][2]);
        float2 c3 = unp(accp[p][3]);
        int m = bm + ty*8 + 2*p;
        *(float4*)&Uout[(size_t)m*Nc + n0]     = make_float4(c0.x, c1.x, c2.x, c3.x);
        *(float4*)&Uout[(size_t)(m+1)*Nc + n0] = make_float4(c0.y, c1.y, c2.y, c3.y);
    }
}

// =============== combine: K = SCALE*(P + Q*(U0+U1)) (+jitter) ===============
#define S0F4 327680   // Kzx float4 count
#define S1F4 40960    // Kzz
#define S2F4 81920    // Ktz
__global__ void kcombine() {
    const int gtid = blockIdx.x*256 + threadIdx.x;   // 440*256 = 112640
    #pragma unroll
    for (int it = 0; it < 4; ++it) {
        int f4 = gtid + it*112640;
        float4 u0, u1, pp, qq; float4* dst; int jm = -1, jn0 = 0;
        if (f4 < S0F4) {
            int rem = f4 & 32767;
            int m = rem >> 8, n0 = (rem & 255) << 2;
            u0 = ((const float4*)g_Uzx)[f4];
            u1 = ((const float4*)g_Uzx)[S0F4 + f4];
            pp = *(const float4*)&g_Pzx[m*N_DATA + n0];
            qq = *(const float4*)&g_Qzx[m*N_DATA + n0];
            dst = ((float4*)g_Kzx) + f4;
        } else if (f4 < S0F4 + S1F4) {
            int f = f4 - S0F4;
            int rem = f & 4095;
            int m = rem >> 5, n0 = (rem & 31) << 2;
            u0 = ((const float4*)g_Uzz)[f];
            u1 = ((const float4*)g_Uzz)[S1F4 + f];
            pp = *(const float4*)&g_Pzz[m*M_IND + n0];
            qq = *(const float4*)&g_Qzz[m*M_IND + n0];
            dst = ((float4*)g_Kzz) + f;
            jm = m; jn0 = n0;
        } else {
            int f = f4 - S0F4 - S1F4;
            int rem = f & 8191;
            int m = rem >> 5, n0 = (rem & 31) << 2;
            u0 = ((const float4*)g_Utz)[f];
            u1 = ((const float4*)g_Utz)[S2F4 + f];
            pp = *(const float4*)&g_Ptz[m*M_IND + n0];
            qq = *(const float4*)&g_Qtz[m*M_IND + n0];
            dst = ((float4*)g_Ktz) + f;
        }
        float4 o;
        o.x = SCALE_K*(pp.x + qq.x*(u0.x + u1.x));
        o.y = SCALE_K*(pp.y + qq.y*(u0.y + u1.y));
        o.z = SCALE_K*(pp.z + qq.z*(u0.z + u1.z));
        o.w = SCALE_K*(pp.w + qq.w*(u0.w + u1.w));
        if (jm >= jn0 && jm < jn0 + 4) {
            if (jm == jn0)   o.x += JITTER_K;
            if (jm == jn0+1) o.y += JITTER_K;
            if (jm == jn0+2) o.z += JITTER_K;
            if (jm == jn0+3) o.w += JITTER_K;
        }
        *dst = o;
    }
}

// =============== Bpart symmetric split-K8 (240 blocks) + alpha (40) ===============
__global__ void bgemm_alpha() {
    const int tid = threadIdx.x;
    const int j = blockIdx.x;
    if (j < 240) {
        __shared__ __align__(16) float As[16][68];
        __shared__ __align__(16) float Bs[16][68];
        const int i = j / 24, r = j - i*24;
        const int tt = r % 3, kc = r / 3;          // kc 0..7
        const int mt = (tt == 2) ? 1 : 0;
        const int nt = (tt == 0) ? 0 : 1;
        const float* A = g_Kzx + (size_t)i*M_IND*N_DATA;
        const int bm = mt*64, bn = nt*64, kbeg = kc*128;
        const int lrow = tid >> 1, lk = (tid & 1) << 3;
        const int tx = tid & 15, ty = tid >> 4;
        ull accp[4][4] = {};
        for (int k0 = kbeg; k0 < kbeg+128; k0 += 16) {
            float4 a0 = *(const float4*)&A[(bm+lrow)*N_DATA + k0 + lk];
            float4 a1 = *(const float4*)&A[(bm+lrow)*N_DATA + k0 + lk + 4];
            float4 b0 = *(const float4*)&A[(bn+lrow)*N_DATA + k0 + lk];
            float4 b1 = *(const float4*)&A[(bn+lrow)*N_DATA + k0 + lk + 4];
            __syncthreads();
            As[lk+0][lrow]=a0.x; As[lk+1][lrow]=a0.y; As[lk+2][lrow]=a0.z; As[lk+3][lrow]=a0.w;
            As[lk+4][lrow]=a1.x; As[lk+5][lrow]=a1.y; As[lk+6][lrow]=a1.z; As[lk+7][lrow]=a1.w;
            Bs[lk+0][lrow]=b0.x; Bs[lk+1][lrow]=b0.y; Bs[lk+2][lrow]=b0.z; Bs[lk+3][lrow]=b0.w;
            Bs[lk+4][lrow]=b1.x; Bs[lk+5][lrow]=b1.y; Bs[lk+6][lrow]=b1.z; Bs[lk+7][lrow]=b1.w;
            __syncthreads();
            #pragma unroll
            for (int kk = 0; kk < 16; ++kk) {
                ull ap[4];
                ap[0] = *(const ull*)&As[kk][ty*8 + 0];
                ap[1] = *(const ull*)&As[kk][ty*8 + 2];
                ap[2] = *(const ull*)&As[kk][ty*8 + 4];
                ap[3] = *(const ull*)&As[kk][ty*8 + 6];
                float4 b4 = *(const float4*)&Bs[kk][tx*4];
                ull db[4] = {dup2(b4.x), dup2(b4.y), dup2(b4.z), dup2(b4.w)};
                #pragma unroll
                for (int p = 0; p < 4; ++p)
                    #pragma unroll
                    for (int v = 0; v < 4; ++v) fma2(accp[p][v], ap[p], db[v]);
            }
        }
        float* outp = g_Bpart + ((size_t)(kc*C_OUT + i)*M_IND)*M_IND;
        const int n0 = bn + tx*4;
        #pragma unroll
        for (int p = 0; p < 4; ++p) {
            float2 cc[4];
            cc[0] = unp(accp[p][0]); cc[1] = unp(accp[p][1]);
            cc[2] = unp(accp[p][2]); cc[3] = unp(accp[p][3]);
            int m = bm + ty*8 + 2*p;
            *(float4*)&outp[m*M_IND + n0] =
                make_float4(2.f*cc[0].x, 2.f*cc[1].x, 2.f*cc[2].x, 2.f*cc[3].x);
            *(float4*)&outp[(m+1)*M_IND + n0] =
                make_float4(2.f*cc[0].y, 2.f*cc[1].y, 2.f*cc[2].y, 2.f*cc[3].y);
            if (tt == 1) {
                #pragma unroll
                for (int v = 0; v < 4; ++v) {
                    outp[(n0+v)*M_IND + m]   = 2.f*cc[v].x;
                    outp[(n0+v)*M_IND + m+1] = 2.f*cc[v].y;
                }
            }
        }
    } else {
        int k = j - 240;
        int i = k >> 2, rb = (k & 3) * 32;
        int w = tid >> 5, lane = tid & 31;
        #pragma unroll
        for (int rr = 0; rr < 8; ++rr) {
            int m = rb + w*8 + rr;
            const float* row = g_Kzx + ((size_t)i*M_IND + m)*N_DATA;
            float acc = 0.f;
            for (int n = lane; n < N_DATA; n += 32) acc += row[n] * g_LAM[n*C_OUT + i];
            #pragma unroll
            for (int o = 16; o; o >>= 1) acc += __shfl_down_sync(0xffffffffu, acc, o);
            if (lane == 0) g_alpha[i*M_IND + m] = acc;
        }
    }
}

// =============== register-tiled right-looking Cholesky (no spills) ===============
__global__ void __launch_bounds__(256) chol_all() {
    const int s = blockIdx.x, tid = threadIdx.x;
    const int isB = (s >= C_OUT);
    const int i = isB ? s - C_OUT : s;
    const float* A0 = g_Kzz + (size_t)i*M_IND*M_IND;
    const int tr = tid >> 4, tc = tid & 15;
    const int r0 = tr*8, c0 = tc*8;
    float a[8][8];
    #pragma unroll
    for (int u = 0; u < 8; ++u) {
        #pragma unroll
        for (int v = 0; v < 8; v += 4) {
            float4 x = *(const float4*)&A0[(r0+u)*M_IND + c0 + v];
            a[u][v]=x.x; a[u][v+1]=x.y; a[u][v+2]=x.z; a[u][v+3]=x.w;
            if (isB) {
                #pragma unroll
                for (int p = 0; p < 8; ++p) {
                    float4 y = *(const float4*)&g_Bpart[((size_t)(p*C_OUT+i)*M_IND + r0+u)*M_IND + c0+v];
                    a[u][v]+=y.x; a[u][v+1]+=y.y; a[u][v+2]+=y.z; a[u][v+3]+=y.w;
                }
            }
        }
    }
    __shared__ float colbuf[2][M_IND];
    for (int jb = 0; jb < 16; ++jb) {
        const bool owner = (tc == jb);
        #pragma unroll
        for (int v = 0; v < 8; ++v) {
            const int j = jb*8 + v;
            float* col = colbuf[v & 1];
            if (owner) {
                #pragma unroll
                for (int u = 0; u < 8; ++u) col[r0 + u] = a[u][v];
            }
            __syncthreads();
            const float djj = col[j];
            const float dinv = rsqrtf(djj);
            float ci[8], ck[8];
            #pragma unroll
            for (int u = 0; u < 8; ++u) {
                int ri = r0 + u;
                ci[u] = (ri > j) ? col[ri] * dinv : 0.f;
            }
            #pragma unroll
            for (int w = 0; w < 8; ++w) {
                int kk = c0 + w;
                ck[w] = (kk > j) ? col[kk] * dinv : 0.f;
            }
            if (owner) {
                #pragma unroll
                for (int u = 0; u < 8; ++u) {
                    int ri = r0 + u;
                    if (ri > j)       a[u][v] = ci[u];
                    else if (ri == j) a[u][v] = djj * dinv;
                }
            }
            #pragma unroll
            for (int u = 0; u < 8; ++u)
                #pragma unroll
                for (int w = 0; w < 8; ++w)
                    a[u][w] = fmaf(-ci[u], ck[w], a[u][w]);
        }
    }
    float* out = isB ? (g_LB + i*LPACK) : (g_LKzz + i*LPACK);
    if (c0 <= r0 + 7) {
        #pragma unroll
        for (int u = 0; u < 8; ++u) {
            int ri = r0 + u;
            if (ri >= c0) {
                int base = (ri*(ri+1)) >> 1;
                #pragma unroll
                for (int w = 0; w < 8; ++w) {
                    int kk = c0 + w;
                    if (kk <= ri) out[base + kk] = a[u][w];
                }
            }
        }
    }
}

// =============== solves: 160 fs blocks (4 solves/warp) + 10 meansolve ===============
__global__ void solve_all() {
    __shared__ float Lp[LPACK];
    __shared__ float dinv[M_IND];
    __shared__ float ysm[M_IND];
    const int b = blockIdx.x, tid = threadIdx.x;
    const int w = tid >> 5, lane = tid & 31;
    if (b < 160) {
        const int s = b >> 3;
        const int t0 = (b & 7)*32 + w*4;
        const int i = (s < C_OUT) ? s : s - C_OUT;
        const float* Ls = (s < C_OUT) ? (g_LKzz + s*LPACK) : (g_LB + (s-C_OUT)*LPACK);
        for (int idx = tid; idx < LPACK; idx += 256) Lp[idx] = Ls[idx];
        if (tid < M_IND) dinv[tid] = 1.0f / Ls[((tid*(tid+1))>>1) + tid];
        __syncthreads();
        float br[4][4];
        int base[4];
        #pragma unroll
        for (int r = 0; r < 4; ++r) {
            int row = r*32 + lane;
            base[r] = (row*(row+1)) >> 1;
        }
        #pragma unroll
        for (int tl = 0; tl < 4; ++tl) {
            const float* bvec = g_Ktz + ((size_t)i*NT_PTS + t0 + tl)*M_IND;
            #pragma unroll
            for (int r = 0; r < 4; ++r) br[tl][r] = bvec[lane + 32*r];
        }
        float ss[4] = {0.f, 0.f, 0.f, 0.f};
        #pragma unroll
        for (int oreg = 0; oreg < 4; ++oreg) {
            for (int jj = 0; jj < 32; ++jj) {
                int jc = oreg*32 + jj;
                float dv = dinv[jc];
                float Lv0 = Lp[base[oreg] + jc];
                float Lv1 = (oreg < 3) ? Lp[base[oreg < 3 ? oreg+1 : 3] + jc] : 0.f;
                float Lv2 = (oreg < 2) ? Lp[base[oreg < 2 ? oreg+2 : 3] + jc] : 0.f;
                float Lv3 = (oreg < 1) ? Lp[base[3] + jc] : 0.f;
                #pragma unroll
                for (int tl = 0; tl < 4; ++tl) {
                    float yj = __shfl_sync(0xffffffffu, br[tl][oreg], jj) * dv;
                    ss[tl] = fmaf(yj, yj, ss[tl]);
                    if (lane > jj) br[tl][oreg] -= Lv0 * yj;
                    if (oreg < 3) br[tl][oreg+1 < 4 ? oreg+1 : 3] -= Lv1 * yj;
                    if (oreg < 2) br[tl][oreg+2 < 4 ? oreg+2 : 3] -= Lv2 * yj;
                    if (oreg < 1) br[tl][3] -= Lv3 * yj;
                }
            }
        }
        if (lane == 0) {
            #pragma unroll
            for (int tl = 0; tl < 4; ++tl) {
                if (s < C_OUT) g_SSZ[i*NT_PTS + t0 + tl] = ss[tl];
                else           g_SSB[i*NT_PTS + t0 + tl] = ss[tl];
            }
        }
    } else {
        const int i = b - 160;
        const float* Ls = g_LB + i*LPACK;
        for (int idx = tid; idx < LPACK; idx += 256) Lp[idx] = Ls[idx];
        if (tid < M_IND) dinv[tid] = 1.0f / Ls[((tid*(tid+1))>>1) + tid];
        __syncthreads();
        if (w != 0) return;
        float br[4]; int base[4];
        #pragma unroll
        for (int r = 0; r < 4; ++r) {
            br[r] = g_alpha[i*M_IND + lane + 32*r];
            int row = r*32 + lane;
            base[r] = (row*(row+1)) >> 1;
        }
        #pragma unroll
        for (int oreg = 0; oreg < 4; ++oreg) {
            for (int jj = 0; jj < 32; ++jj) {
                int jc = oreg*32 + jj;
                float yj = __shfl_sync(0xffffffffu, br[oreg], jj) * dinv[jc];
                if (lane == 0) ysm[jc] = yj;
                if (lane > jj) br[oreg] -= Lp[base[oreg] + jc] * yj;
                #pragma unroll
                for (int r = oreg+1; r < 4; ++r) br[r] -= Lp[base[r] + jc] * yj;
            }
        }
        __syncwarp();
        float xr[4];
        #pragma unroll
        for (int r = 0; r < 4; ++r) xr[r] = ysm[r*32 + lane];
        #pragma unroll
        for (int oreg = 3; oreg >= 0; --oreg) {
            for (int jj = 31; jj >= 0; --jj) {
                int jc = oreg*32 + jj;
                float xj = __shfl_sync(0xffffffffu, xr[oreg], jj) * dinv[jc];
                if (lane == 0) g_cvec[i*M_IND + jc] = xj;
                int rb2 = (jc*(jc+1)) >> 1;
                if (lane < jj) xr[oreg] -= Lp[rb2 + oreg*32 + lane] * xj;
                #pragma unroll
                for (int r = 0; r < 4; ++r)
                    if (r < oreg) xr[r] -= Lp[rb2 + r*32 + lane] * xj;
            }
        }
    }
}

// =============== epilogue: mean + variance ===============
__global__ void epilogue(const float* __restrict__ Xt, const float* __restrict__ W2,
                         float* __restrict__ out) {
    const int gw = blockIdx.x*8 + (threadIdx.x >> 5);
    const int lane = threadIdx.x & 31;
    const int t = gw / C_OUT, i = gw - t*C_OUT;
    float accU = 0.f, ph = 0.f, qx = 0.f;
    for (int k = lane; k < H_DIM; k += 32) {
        float s = g_ST[t*H_DIM + k];
        float h = g_HT[t*H_DIM + k];
        float w = W2[k*C_OUT + i];
        accU = fmaf(s*s, w*w, accU);
        ph = fmaf(h, h, ph);
    }
    for (int k = lane; k < D_IN; k += 32) { float x = Xt[t*D_IN + k]; qx = fmaf(x, x, qx); }
    float mean = 0.f;
    const float* kr = g_Ktz + ((size_t)i*NT_PTS + t)*M_IND;
    const float* cr = g_cvec + i*M_IND;
    #pragma unroll
    for (int r = 0; r < 4; ++r) mean += kr[lane + 32*r] * cr[lane + 32*r];
    #pragma unroll
    for (int o = 16; o; o >>= 1) {
        accU += __shfl_xor_sync(0xffffffffu, accU, o);
        ph   += __shfl_xor_sync(0xffffffffu, ph, o);
        qx   += __shfl_xor_sync(0xffffffffu, qx, o);
        mean += __shfl_xor_sync(0xffffffffu, mean, o);
    }
    if (lane == 0) {
        float kttd = SCALE_K * ((ph + 1.f) + (qx + 1.f)*accU);
        out[t*C_OUT + i] = mean;
        out[NT_PTS*C_OUT + t*C_OUT + i] = kttd - g_SSZ[i*NT_PTS + t] + g_SSB[i*NT_PTS + t];
    }
}

extern "C" void kernel_launch(void* const* d_in, const int* in_sizes, int n_in,
                              void* d_out, int out_size) {
    const float* X  = (const float*)d_in[0];
    const float* Y  = (const float*)d_in[1];
    const float* Z  = (const float*)d_in[2];
    const float* Xt = (const float*)d_in[3];
    const float* W1 = (const float*)d_in[4];
    const float* b1 = (const float*)d_in[5];
    const float* W2 = (const float*)d_in[6];
    const float* b2 = (const float*)d_in[7];
    float* out = (float*)d_out;

    fwd_all<<<dim3(6,44), 128>>>(X, Z, Xt, W1, b1);
    pq_lam<<<432, 128>>>(X, Z, Xt, Y, W2, b2);
    kbuild_all<<<880, 128>>>(W2);
    kcombine<<<440, 256>>>();
    bgemm_alpha<<<280, 128>>>();
    chol_all<<<20, 256>>>();
    solve_all<<<170, 256>>>();
    epilogue<<<320, 256>>>(Xt, W2, out);
}

// round 14
// speedup vs baseline: 1.2383x; 1.0740x over previous
#include <cuda_runtime.h>

#define N_DATA 1024
#define D_IN   256
#define H_DIM  384
#define C_OUT  10
#define M_IND  128
#define NT_PTS 256
#define SCALE_K (1.0f/1024.0f)
#define JITTER_K 1e-3f
#define LPACK (M_IND*(M_IND+1)/2)

typedef unsigned long long ull;

// ---------------- device scratch ----------------
__device__ float g_HX[N_DATA*H_DIM];
__device__ float g_SX[N_DATA*H_DIM];
__device__ float g_HZ[M_IND*H_DIM];
__device__ float g_SZ[M_IND*H_DIM];
__device__ float g_HT[NT_PTS*H_DIM];
__device__ float g_ST[NT_PTS*H_DIM];
__device__ float g_LAM[N_DATA*C_OUT];
__device__ float g_Pzx[M_IND*N_DATA];
__device__ float g_Qzx[M_IND*N_DATA];
__device__ float g_Pzz[M_IND*M_IND];
__device__ float g_Qzz[M_IND*M_IND];
__device__ float g_Ptz[NT_PTS*M_IND];
__device__ float g_Qtz[NT_PTS*M_IND];
__device__ float g_Uzx[2*C_OUT*M_IND*N_DATA];
__device__ float g_Uzz[2*C_OUT*M_IND*M_IND];
__device__ float g_Utz[2*C_OUT*NT_PTS*M_IND];
__device__ float g_Kzx[C_OUT*M_IND*N_DATA];
__device__ float g_Kzz[C_OUT*M_IND*M_IND];
__device__ float g_Ktz[C_OUT*NT_PTS*M_IND];
__device__ float g_Bpart[8*C_OUT*M_IND*M_IND];
__device__ float g_LKzz[C_OUT*LPACK];
__device__ float g_LB[C_OUT*LPACK];
__device__ float g_alpha[C_OUT*M_IND];
__device__ float g_cvec[C_OUT*M_IND];
__device__ float g_SSZ[C_OUT*NT_PTS];
__device__ float g_SSB[C_OUT*NT_PTS];

// ---------------- f32x2 packed helpers ----------------
__device__ __forceinline__ ull dup2(float x) {
    ull r; unsigned u = __float_as_uint(x);
    asm("mov.b64 %0, {%1, %1};" : "=l"(r) : "r"(u));
    return r;
}
__device__ __forceinline__ void fma2(ull& d, ull a, ull b) {
    asm("fma.rn.f32x2 %0, %1, %2, %0;" : "+l"(d) : "l"(a), "l"(b));
}
__device__ __forceinline__ float2 unp(ull v) {
    float2 f;
    asm("mov.b64 {%0, %1}, %2;" : "=f"(f.x), "=f"(f.y) : "l"(v));
    return f;
}

// =============== forward: 32-row tiles, grid (6,44), 128 thr, 4x4/thread ===============
__global__ void fwd_all(const float* __restrict__ X, const float* __restrict__ Z,
                        const float* __restrict__ T, const float* __restrict__ W1,
                        const float* __restrict__ b1) {
    __shared__ __align__(16) float As[16][36];
    __shared__ __align__(16) float Bs[16][68];
    const int tid = threadIdx.x;
    const int rb = blockIdx.y, nb = blockIdx.x;
    const float* src; float* Hd; float* Sd; int row0;
    if (rb < 32)      { src = X; Hd = g_HX; Sd = g_SX; row0 = rb*32; }
    else if (rb < 36) { src = Z; Hd = g_HZ; Sd = g_SZ; row0 = (rb-32)*32; }
    else              { src = T; Hd = g_HT; Sd = g_ST; row0 = (rb-36)*32; }
    const int arow = tid >> 2, aq = (tid & 3) << 2;
    const int kr = tid >> 3, nq = (tid & 7) << 3;
    const int tx = tid & 15, ty = tid >> 4;
    float acc[4][4] = {};
    for (int k0 = 0; k0 < D_IN; k0 += 16) {
        float4 av = *(const float4*)&src[(row0+arow)*D_IN + k0 + aq];
        float4 b0 = *(const float4*)&W1[(k0+kr)*H_DIM + nb*64 + nq];
        float4 b1v= *(const float4*)&W1[(k0+kr)*H_DIM + nb*64 + nq + 4];
        __syncthreads();
        As[aq+0][arow]=av.x; As[aq+1][arow]=av.y; As[aq+2][arow]=av.z; As[aq+3][arow]=av.w;
        *(float4*)&Bs[kr][nq] = b0; *(float4*)&Bs[kr][nq+4] = b1v;
        __syncthreads();
        #pragma unroll
        for (int kk = 0; kk < 16; ++kk) {
            float4 a4 = *(const float4*)&As[kk][ty*4];
            float4 b4 = *(const float4*)&Bs[kk][tx*4];
            float a[4] = {a4.x,a4.y,a4.z,a4.w};
            float b[4] = {b4.x,b4.y,b4.z,b4.w};
            #pragma unroll
            for (int u = 0; u < 4; ++u)
                #pragma unroll
                for (int v = 0; v < 4; ++v) acc[u][v] = fmaf(a[u], b[v], acc[u][v]);
        }
    }
    const int n0 = nb*64 + tx*4;
    float4 bv = *(const float4*)&b1[n0];
    #pragma unroll
    for (int u = 0; u < 4; ++u) {
        int m = row0 + ty*4 + u;
        float4 h4, s4;
        h4.x = tanhf(acc[u][0]+bv.x); h4.y = tanhf(acc[u][1]+bv.y);
        h4.z = tanhf(acc[u][2]+bv.z); h4.w = tanhf(acc[u][3]+bv.w);
        s4.x = 1.f-h4.x*h4.x; s4.y = 1.f-h4.y*h4.y;
        s4.z = 1.f-h4.z*h4.z; s4.w = 1.f-h4.w*h4.w;
        *(float4*)&Hd[m*H_DIM + n0] = h4;
        *(float4*)&Sd[m*H_DIM + n0] = s4;
    }
}

// =============== MERGED stage 2: kbuild (0..879) + pq (880..1055) + lam (1056..1311) ===============
__global__ void stage2(const float* __restrict__ X, const float* __restrict__ Z,
                       const float* __restrict__ T, const float* __restrict__ Y,
                       const float* __restrict__ W2, const float* __restrict__ b2) {
    const int tid = threadIdx.x;
    const int bj = blockIdx.x;
    if (bj < 880) {
        // ---- kbuild: U partials, split-K=2, FFMA2 ----
        __shared__ __align__(16) float As[16][68];
        __shared__ __align__(16) float Bs[16][68];
        __shared__ float ws[H_DIM];
        const int half = (bj >= 440) ? 1 : 0;
        const int j = bj - half*440;
        const float *Sa, *Sb; float* Uout; int Nc, mt, nt, i;
        if (j < 320)      { i=j>>5; int r=j&31; mt=r>>4; nt=r&15; Sa=g_SZ; Sb=g_SX;
                            Uout=g_Uzx + ((size_t)half*C_OUT + i)*M_IND*N_DATA; Nc=N_DATA; }
        else if (j < 360) { i=(j-320)>>2; int r=(j-320)&3; mt=r>>1; nt=r&1; Sa=g_SZ; Sb=g_SZ;
                            Uout=g_Uzz + ((size_t)half*C_OUT + i)*M_IND*M_IND; Nc=M_IND; }
        else              { i=(j-360)>>3; int r=(j-360)&7; mt=r>>1; nt=r&1; Sa=g_ST; Sb=g_SZ;
                            Uout=g_Utz + ((size_t)half*C_OUT + i)*NT_PTS*M_IND; Nc=M_IND; }
        for (int k = tid; k < H_DIM; k += 128) { float w = W2[k*C_OUT + i]; ws[k] = w*w; }
        const int bm = mt*64, bn = nt*64;
        const int lrow = tid >> 1, lk = (tid & 1) << 3;
        const int tx = tid & 15, ty = tid >> 4;
        const int kbeg = half*192, kend = kbeg + 192;
        ull accp[4][4] = {};
        for (int k0 = kbeg; k0 < kend; k0 += 16) {
            float4 a0 = *(const float4*)&Sa[(bm+lrow)*H_DIM + k0 + lk];
            float4 a1 = *(const float4*)&Sa[(bm+lrow)*H_DIM + k0 + lk + 4];
            float4 b0 = *(const float4*)&Sb[(bn+lrow)*H_DIM + k0 + lk];
            float4 b1 = *(const float4*)&Sb[(bn+lrow)*H_DIM + k0 + lk + 4];
            __syncthreads();
            As[lk+0][lrow]=a0.x*ws[k0+lk+0]; As[lk+1][lrow]=a0.y*ws[k0+lk+1];
            As[lk+2][lrow]=a0.z*ws[k0+lk+2]; As[lk+3][lrow]=a0.w*ws[k0+lk+3];
            As[lk+4][lrow]=a1.x*ws[k0+lk+4]; As[lk+5][lrow]=a1.y*ws[k0+lk+5];
            As[lk+6][lrow]=a1.z*ws[k0+lk+6]; As[lk+7][lrow]=a1.w*ws[k0+lk+7];
            Bs[lk+0][lrow]=b0.x; Bs[lk+1][lrow]=b0.y; Bs[lk+2][lrow]=b0.z; Bs[lk+3][lrow]=b0.w;
            Bs[lk+4][lrow]=b1.x; Bs[lk+5][lrow]=b1.y; Bs[lk+6][lrow]=b1.z; Bs[lk+7][lrow]=b1.w;
            __syncthreads();
            #pragma unroll
            for (int kk = 0; kk < 16; ++kk) {
                ull ap[4];
                ap[0] = *(const ull*)&As[kk][ty*8 + 0];
                ap[1] = *(const ull*)&As[kk][ty*8 + 2];
                ap[2] = *(const ull*)&As[kk][ty*8 + 4];
                ap[3] = *(const ull*)&As[kk][ty*8 + 6];
                float4 b4 = *(const float4*)&Bs[kk][tx*4];
                ull db[4] = {dup2(b4.x), dup2(b4.y), dup2(b4.z), dup2(b4.w)};
                #pragma unroll
                for (int p = 0; p < 4; ++p)
                    #pragma unroll
                    for (int v = 0; v < 4; ++v) fma2(accp[p][v], ap[p], db[v]);
            }
        }
        const int n0 = bn + tx*4;
        #pragma unroll
        for (int p = 0; p < 4; ++p) {
            float2 c0 = unp(accp[p][0]);
            float2 c1 = unp(accp[p][1]);
            float2 c2 = unp(accp[p][2]);
            float2 c3 = unp(accp[p][3]);
            int m = bm + ty*8 + 2*p;
            *(float4*)&Uout[(size_t)m*Nc + n0]     = make_float4(c0.x, c1.x, c2.x, c3.x);
            *(float4*)&Uout[(size_t)(m+1)*Nc + n0] = make_float4(c0.y, c1.y, c2.y, c3.y);
        }
    } else if (bj < 1056) {
        // ---- pq grams: 176 jobs ----
        __shared__ __align__(16) float As2[16][36];
        __shared__ __align__(16) float Bs2[16][68];
        int j = bj - 880;
        const int isQ = (j >= 88); if (isQ) j -= 88;
        const float *Ap, *Bp; float* outp; int Nc, mt, nt;
        if (j < 64)      { mt=j>>4;      nt=j&15;     Ap=isQ?Z:g_HZ; Bp=isQ?X:g_HX; outp=isQ?g_Qzx:g_Pzx; Nc=N_DATA; }
        else if (j < 72) { int q=j-64; mt=q>>1; nt=q&1; Ap=isQ?Z:g_HZ; Bp=isQ?Z:g_HZ; outp=isQ?g_Qzz:g_Pzz; Nc=M_IND; }
        else             { int q=j-72; mt=q>>1; nt=q&1; Ap=isQ?T:g_HT; Bp=isQ?Z:g_HZ; outp=isQ?g_Qtz:g_Ptz; Nc=M_IND; }
        const int K = isQ ? D_IN : H_DIM;
        const int bm = mt*32, bn = nt*64;
        const int arow = tid >> 2, aq = (tid & 3) << 2;
        const int lrow = tid >> 1, lk = (tid & 1) << 3;
        const int tx = tid & 15, ty = tid >> 4;
        float acc[4][4] = {};
        for (int k0 = 0; k0 < K; k0 += 16) {
            float4 av = *(const float4*)&Ap[(bm+arow)*K + k0 + aq];
            float4 b0 = *(const float4*)&Bp[(bn+lrow)*K + k0 + lk];
            float4 b1 = *(const float4*)&Bp[(bn+lrow)*K + k0 + lk + 4];
            __syncthreads();
            As2[aq+0][arow]=av.x; As2[aq+1][arow]=av.y; As2[aq+2][arow]=av.z; As2[aq+3][arow]=av.w;
            Bs2[lk+0][lrow]=b0.x; Bs2[lk+1][lrow]=b0.y; Bs2[lk+2][lrow]=b0.z; Bs2[lk+3][lrow]=b0.w;
            Bs2[lk+4][lrow]=b1.x; Bs2[lk+5][lrow]=b1.y; Bs2[lk+6][lrow]=b1.z; Bs2[lk+7][lrow]=b1.w;
            __syncthreads();
            #pragma unroll
            for (int kk = 0; kk < 16; ++kk) {
                float4 a4 = *(const float4*)&As2[kk][ty*4];
                float4 b4 = *(const float4*)&Bs2[kk][tx*4];
                float a[4] = {a4.x,a4.y,a4.z,a4.w};
                float b[4] = {b4.x,b4.y,b4.z,b4.w};
                #pragma unroll
                for (int u = 0; u < 4; ++u)
                    #pragma unroll
                    for (int v = 0; v < 4; ++v) acc[u][v] = fmaf(a[u], b[v], acc[u][v]);
            }
        }
        const int n0 = bn + tx*4;
        #pragma unroll
        for (int u = 0; u < 4; ++u) {
            int m = bm + ty*4 + u;
            float4 o4 = {acc[u][0]+1.f, acc[u][1]+1.f, acc[u][2]+1.f, acc[u][3]+1.f};
            *(float4*)&outp[(size_t)m*Nc + n0] = o4;
        }
    } else {
        // ---- lambda: 256 blocks x 4 rows ----
        int warp = tid >> 5, lane = tid & 31;
        int row = (bj - 1056)*4 + warp;
        float h[12];
        #pragma unroll
        for (int r = 0; r < 12; ++r) h[r] = g_HX[row*H_DIM + lane + r*32];
        #pragma unroll
        for (int c = 0; c < C_OUT; ++c) {
            float acc = 0.f;
            #pragma unroll
            for (int r = 0; r < 12; ++r) acc += h[r] * W2[(lane + r*32)*C_OUT + c];
            #pragma unroll
            for (int o = 16; o; o >>= 1) acc += __shfl_down_sync(0xffffffffu, acc, o);
            if (lane == 0) g_LAM[row*C_OUT + c] = acc + b2[c] + Y[row*C_OUT + c];
        }
    }
}

// =============== combine: K = SCALE*(P + Q*(U0+U1)) (+jitter) ===============
#define S0F4 327680
#define S1F4 40960
#define S2F4 81920
__global__ void kcombine() {
    const int gtid = blockIdx.x*256 + threadIdx.x;
    #pragma unroll
    for (int it = 0; it < 4; ++it) {
        int f4 = gtid + it*112640;
        float4 u0, u1, pp, qq; float4* dst; int jm = -1, jn0 = 0;
        if (f4 < S0F4) {
            int rem = f4 & 32767;
            int m = rem >> 8, n0 = (rem & 255) << 2;
            u0 = ((const float4*)g_Uzx)[f4];
            u1 = ((const float4*)g_Uzx)[S0F4 + f4];
            pp = *(const float4*)&g_Pzx[m*N_DATA + n0];
            qq = *(const float4*)&g_Qzx[m*N_DATA + n0];
            dst = ((float4*)g_Kzx) + f4;
        } else if (f4 < S0F4 + S1F4) {
            int f = f4 - S0F4;
            int rem = f & 4095;
            int m = rem >> 5, n0 = (rem & 31) << 2;
            u0 = ((const float4*)g_Uzz)[f];
            u1 = ((const float4*)g_Uzz)[S1F4 + f];
            pp = *(const float4*)&g_Pzz[m*M_IND + n0];
            qq = *(const float4*)&g_Qzz[m*M_IND + n0];
            dst = ((float4*)g_Kzz) + f;
            jm = m; jn0 = n0;
        } else {
            int f = f4 - S0F4 - S1F4;
            int rem = f & 8191;
            int m = rem >> 5, n0 = (rem & 31) << 2;
            u0 = ((const float4*)g_Utz)[f];
            u1 = ((const float4*)g_Utz)[S2F4 + f];
            pp = *(const float4*)&g_Ptz[m*M_IND + n0];
            qq = *(const float4*)&g_Qtz[m*M_IND + n0];
            dst = ((float4*)g_Ktz) + f;
        }
        float4 o;
        o.x = SCALE_K*(pp.x + qq.x*(u0.x + u1.x));
        o.y = SCALE_K*(pp.y + qq.y*(u0.y + u1.y));
        o.z = SCALE_K*(pp.z + qq.z*(u0.z + u1.z));
        o.w = SCALE_K*(pp.w + qq.w*(u0.w + u1.w));
        if (jm >= jn0 && jm < jn0 + 4) {
            if (jm == jn0)   o.x += JITTER_K;
            if (jm == jn0+1) o.y += JITTER_K;
            if (jm == jn0+2) o.z += JITTER_K;
            if (jm == jn0+3) o.w += JITTER_K;
        }
        *dst = o;
    }
}

// =============== Bpart symmetric split-K8 (240 blocks) + alpha (40) ===============
__global__ void bgemm_alpha() {
    const int tid = threadIdx.x;
    const int j = blockIdx.x;
    if (j < 240) {
        __shared__ __align__(16) float As[16][68];
        __shared__ __align__(16) float Bs[16][68];
        const int i = j / 24, r = j - i*24;
        const int tt = r % 3, kc = r / 3;
        const int mt = (tt == 2) ? 1 : 0;
        const int nt = (tt == 0) ? 0 : 1;
        const float* A = g_Kzx + (size_t)i*M_IND*N_DATA;
        const int bm = mt*64, bn = nt*64, kbeg = kc*128;
        const int lrow = tid >> 1, lk = (tid & 1) << 3;
        const int tx = tid & 15, ty = tid >> 4;
        ull accp[4][4] = {};
        for (int k0 = kbeg; k0 < kbeg+128; k0 += 16) {
            float4 a0 = *(const float4*)&A[(bm+lrow)*N_DATA + k0 + lk];
            float4 a1 = *(const float4*)&A[(bm+lrow)*N_DATA + k0 + lk + 4];
            float4 b0 = *(const float4*)&A[(bn+lrow)*N_DATA + k0 + lk];
            float4 b1 = *(const float4*)&A[(bn+lrow)*N_DATA + k0 + lk + 4];
            __syncthreads();
            As[lk+0][lrow]=a0.x; As[lk+1][lrow]=a0.y; As[lk+2][lrow]=a0.z; As[lk+3][lrow]=a0.w;
            As[lk+4][lrow]=a1.x; As[lk+5][lrow]=a1.y; As[lk+6][lrow]=a1.z; As[lk+7][lrow]=a1.w;
            Bs[lk+0][lrow]=b0.x; Bs[lk+1][lrow]=b0.y; Bs[lk+2][lrow]=b0.z; Bs[lk+3][lrow]=b0.w;
            Bs[lk+4][lrow]=b1.x; Bs[lk+5][lrow]=b1.y; Bs[lk+6][lrow]=b1.z; Bs[lk+7][lrow]=b1.w;
            __syncthreads();
            #pragma unroll
            for (int kk = 0; kk < 16; ++kk) {
                ull ap[4];
                ap[0] = *(const ull*)&As[kk][ty*8 + 0];
                ap[1] = *(const ull*)&As[kk][ty*8 + 2];
                ap[2] = *(const ull*)&As[kk][ty*8 + 4];
                ap[3] = *(const ull*)&As[kk][ty*8 + 6];
                float4 b4 = *(const float4*)&Bs[kk][tx*4];
                ull db[4] = {dup2(b4.x), dup2(b4.y), dup2(b4.z), dup2(b4.w)};
                #pragma unroll
                for (int p = 0; p < 4; ++p)
                    #pragma unroll
                    for (int v = 0; v < 4; ++v) fma2(accp[p][v], ap[p], db[v]);
            }
        }
        float* outp = g_Bpart + ((size_t)(kc*C_OUT + i)*M_IND)*M_IND;
        const int n0 = bn + tx*4;
        #pragma unroll
        for (int p = 0; p < 4; ++p) {
            float2 cc[4];
            cc[0] = unp(accp[p][0]); cc[1] = unp(accp[p][1]);
            cc[2] = unp(accp[p][2]); cc[3] = unp(accp[p][3]);
            int m = bm + ty*8 + 2*p;
            *(float4*)&outp[m*M_IND + n0] =
                make_float4(2.f*cc[0].x, 2.f*cc[1].x, 2.f*cc[2].x, 2.f*cc[3].x);
            *(float4*)&outp[(m+1)*M_IND + n0] =
                make_float4(2.f*cc[0].y, 2.f*cc[1].y, 2.f*cc[2].y, 2.f*cc[3].y);
            if (tt == 1) {
                #pragma unroll
                for (int v = 0; v < 4; ++v) {
                    outp[(n0+v)*M_IND + m]   = 2.f*cc[v].x;
                    outp[(n0+v)*M_IND + m+1] = 2.f*cc[v].y;
                }
            }
        }
    } else {
        int k = j - 240;
        int i = k >> 2, rb = (k & 3) * 32;
        int w = tid >> 5, lane = tid & 31;
        #pragma unroll
        for (int rr = 0; rr < 8; ++rr) {
            int m = rb + w*8 + rr;
            const float* row = g_Kzx + ((size_t)i*M_IND + m)*N_DATA;
            float acc = 0.f;
            for (int n = lane; n < N_DATA; n += 32) acc += row[n] * g_LAM[n*C_OUT + i];
            #pragma unroll
            for (int o = 16; o; o >>= 1) acc += __shfl_down_sync(0xffffffffu, acc, o);
            if (lane == 0) g_alpha[i*M_IND + m] = acc;
        }
    }
}

// =============== register-tiled right-looking Cholesky (no spills) ===============
__global__ void __launch_bounds__(256) chol_all() {
    const int s = blockIdx.x, tid = threadIdx.x;
    const int isB = (s >= C_OUT);
    const int i = isB ? s - C_OUT : s;
    const float* A0 = g_Kzz + (size_t)i*M_IND*M_IND;
    const int tr = tid >> 4, tc = tid & 15;
    const int r0 = tr*8, c0 = tc*8;
    float a[8][8];
    #pragma unroll
    for (int u = 0; u < 8; ++u) {
        #pragma unroll
        for (int v = 0; v < 8; v += 4) {
            float4 x = *(const float4*)&A0[(r0+u)*M_IND + c0 + v];
            a[u][v]=x.x; a[u][v+1]=x.y; a[u][v+2]=x.z; a[u][v+3]=x.w;
            if (isB) {
                #pragma unroll
                for (int p = 0; p < 8; ++p) {
                    float4 y = *(const float4*)&g_Bpart[((size_t)(p*C_OUT+i)*M_IND + r0+u)*M_IND + c0+v];
                    a[u][v]+=y.x; a[u][v+1]+=y.y; a[u][v+2]+=y.z; a[u][v+3]+=y.w;
                }
            }
        }
    }
    __shared__ float colbuf[2][M_IND];
    for (int jb = 0; jb < 16; ++jb) {
        const bool owner = (tc == jb);
        #pragma unroll
        for (int v = 0; v < 8; ++v) {
            const int j = jb*8 + v;
            float* col = colbuf[v & 1];
            if (owner) {
                #pragma unroll
                for (int u = 0; u < 8; ++u) col[r0 + u] = a[u][v];
            }
            __syncthreads();
            const float djj = col[j];
            const float dinv = rsqrtf(djj);
            float ci[8], ck[8];
            #pragma unroll
            for (int u = 0; u < 8; ++u) {
                int ri = r0 + u;
                ci[u] = (ri > j) ? col[ri] * dinv : 0.f;
            }
            #pragma unroll
            for (int w = 0; w < 8; ++w) {
                int kk = c0 + w;
                ck[w] = (kk > j) ? col[kk] * dinv : 0.f;
            }
            if (owner) {
                #pragma unroll
                for (int u = 0; u < 8; ++u) {
                    int ri = r0 + u;
                    if (ri > j)       a[u][v] = ci[u];
                    else if (ri == j) a[u][v] = djj * dinv;
                }
            }
            #pragma unroll
            for (int u = 0; u < 8; ++u)
                #pragma unroll
                for (int w = 0; w < 8; ++w)
                    a[u][w] = fmaf(-ci[u], ck[w], a[u][w]);
        }
    }
    float* out = isB ? (g_LB + i*LPACK) : (g_LKzz + i*LPACK);
    if (c0 <= r0 + 7) {
        #pragma unroll
        for (int u = 0; u < 8; ++u) {
            int ri = r0 + u;
            if (ri >= c0) {
                int base = (ri*(ri+1)) >> 1;
                #pragma unroll
                for (int w = 0; w < 8; ++w) {
                    int kk = c0 + w;
                    if (kk <= ri) out[base + kk] = a[u][w];
                }
            }
        }
    }
}

// =============== solves: 160 fs blocks (4 solves/warp) + 10 meansolve ===============
__global__ void solve_all() {
    __shared__ float Lp[LPACK];
    __shared__ float dinv[M_IND];
    __shared__ float ysm[M_IND];
    const int b = blockIdx.x, tid = threadIdx.x;
    const int w = tid >> 5, lane = tid & 31;
    if (b < 160) {
        const int s = b >> 3;
        const int t0 = (b & 7)*32 + w*4;
        const int i = (s < C_OUT) ? s : s - C_OUT;
        const float* Ls = (s < C_OUT) ? (g_LKzz + s*LPACK) : (g_LB + (s-C_OUT)*LPACK);
        for (int idx = tid; idx < LPACK; idx += 256) Lp[idx] = Ls[idx];
        if (tid < M_IND) dinv[tid] = 1.0f / Ls[((tid*(tid+1))>>1) + tid];
        __syncthreads();
        float br[4][4];
        int base[4];
        #pragma unroll
        for (int r = 0; r < 4; ++r) {
            int row = r*32 + lane;
            base[r] = (row*(row+1)) >> 1;
        }
        #pragma unroll
        for (int tl = 0; tl < 4; ++tl) {
            const float* bvec = g_Ktz + ((size_t)i*NT_PTS + t0 + tl)*M_IND;
            #pragma unroll
            for (int r = 0; r < 4; ++r) br[tl][r] = bvec[lane + 32*r];
        }
        float ss[4] = {0.f, 0.f, 0.f, 0.f};
        #pragma unroll
        for (int oreg = 0; oreg < 4; ++oreg) {
            for (int jj = 0; jj < 32; ++jj) {
                int jc = oreg*32 + jj;
                float dv = dinv[jc];
                float Lv0 = Lp[base[oreg] + jc];
                float Lv1 = (oreg < 3) ? Lp[base[oreg < 3 ? oreg+1 : 3] + jc] : 0.f;
                float Lv2 = (oreg < 2) ? Lp[base[oreg < 2 ? oreg+2 : 3] + jc] : 0.f;
                float Lv3 = (oreg < 1) ? Lp[base[3] + jc] : 0.f;
                #pragma unroll
                for (int tl = 0; tl < 4; ++tl) {
                    float yj = __shfl_sync(0xffffffffu, br[tl][oreg], jj) * dv;
                    ss[tl] = fmaf(yj, yj, ss[tl]);
                    if (lane > jj) br[tl][oreg] -= Lv0 * yj;
                    if (oreg < 3) br[tl][oreg+1 < 4 ? oreg+1 : 3] -= Lv1 * yj;
                    if (oreg < 2) br[tl][oreg+2 < 4 ? oreg+2 : 3] -= Lv2 * yj;
                    if (oreg < 1) br[tl][3] -= Lv3 * yj;
                }
            }
        }
        if (lane == 0) {
            #pragma unroll
            for (int tl = 0; tl < 4; ++tl) {
                if (s < C_OUT) g_SSZ[i*NT_PTS + t0 + tl] = ss[tl];
                else           g_SSB[i*NT_PTS + t0 + tl] = ss[tl];
            }
        }
    } else {
        const int i = b - 160;
        const float* Ls = g_LB + i*LPACK;
        for (int idx = tid; idx < LPACK; idx += 256) Lp[idx] = Ls[idx];
        if (tid < M_IND) dinv[tid] = 1.0f / Ls[((tid*(tid+1))>>1) + tid];
        __syncthreads();
        if (w != 0) return;
        float br[4]; int base[4];
        #pragma unroll
        for (int r = 0; r < 4; ++r) {
            br[r] = g_alpha[i*M_IND + lane + 32*r];
            int row = r*32 + lane;
            base[r] = (row*(row+1)) >> 1;
        }
        #pragma unroll
        for (int oreg = 0; oreg < 4; ++oreg) {
            for (int jj = 0; jj < 32; ++jj) {
                int jc = oreg*32 + jj;
                float yj = __shfl_sync(0xffffffffu, br[oreg], jj) * dinv[jc];
                if (lane == 0) ysm[jc] = yj;
                if (lane > jj) br[oreg] -= Lp[base[oreg] + jc] * yj;
                #pragma unroll
                for (int r = oreg+1; r < 4; ++r) br[r] -= Lp[base[r] + jc] * yj;
            }
        }
        __syncwarp();
        float xr[4];
        #pragma unroll
        for (int r = 0; r < 4; ++r) xr[r] = ysm[r*32 + lane];
        #pragma unroll
        for (int oreg = 3; oreg >= 0; --oreg) {
            for (int jj = 31; jj >= 0; --jj) {
                int jc = oreg*32 + jj;
                float xj = __shfl_sync(0xffffffffu, xr[oreg], jj) * dinv[jc];
                if (lane == 0) g_cvec[i*M_IND + jc] = xj;
                int rb2 = (jc*(jc+1)) >> 1;
                if (lane < jj) xr[oreg] -= Lp[rb2 + oreg*32 + lane] * xj;
                #pragma unroll
                for (int r = 0; r < 4; ++r)
                    if (r < oreg) xr[r] -= Lp[rb2 + r*32 + lane] * xj;
            }
        }
    }
}

// =============== epilogue: mean + variance ===============
__global__ void epilogue(const float* __restrict__ Xt, const float* __restrict__ W2,
                         float* __restrict__ out) {
    const int gw = blockIdx.x*8 + (threadIdx.x >> 5);
    const int lane = threadIdx.x & 31;
    const int t = gw / C_OUT, i = gw - t*C_OUT;
    float accU = 0.f, ph = 0.f, qx = 0.f;
    for (int k = lane; k < H_DIM; k += 32) {
        float s = g_ST[t*H_DIM + k];
        float h = g_HT[t*H_DIM + k];
        float w = W2[k*C_OUT + i];
        accU = fmaf(s*s, w*w, accU);
        ph = fmaf(h, h, ph);
    }
    for (int k = lane; k < D_IN; k += 32) { float x = Xt[t*D_IN + k]; qx = fmaf(x, x, qx); }
    float mean = 0.f;
    const float* kr = g_Ktz + ((size_t)i*NT_PTS + t)*M_IND;
    const float* cr = g_cvec + i*M_IND;
    #pragma unroll
    for (int r = 0; r < 4; ++r) mean += kr[lane + 32*r] * cr[lane + 32*r];
    #pragma unroll
    for (int o = 16; o; o >>= 1) {
        accU += __shfl_xor_sync(0xffffffffu, accU, o);
        ph   += __shfl_xor_sync(0xffffffffu, ph, o);
        qx   += __shfl_xor_sync(0xffffffffu, qx, o);
        mean += __shfl_xor_sync(0xffffffffu, mean, o);
    }
    if (lane == 0) {
        float kttd = SCALE_K * ((ph + 1.f) + (qx + 1.f)*accU);
        out[t*C_OUT + i] = mean;
        out[NT_PTS*C_OUT + t*C_OUT + i] = kttd - g_SSZ[i*NT_PTS + t] + g_SSB[i*NT_PTS + t];
    }
}

extern "C" void kernel_launch(void* const* d_in, const int* in_sizes, int n_in,
                              void* d_out, int out_size) {
    const float* X  = (const float*)d_in[0];
    const float* Y  = (const float*)d_in[1];
    const float* Z  = (const float*)d_in[2];
    const float* Xt = (const float*)d_in[3];
    const float* W1 = (const float*)d_in[4];
    const float* b1 = (const float*)d_in[5];
    const float* W2 = (const float*)d_in[6];
    const float* b2 = (const float*)d_in[7];
    float* out = (float*)d_out;

    fwd_all<<<dim3(6,44), 128>>>(X, Z, Xt, W1, b1);
    stage2<<<1312, 128>>>(X, Z, Xt, Y, W2, b2);
    kcombine<<<440, 256>>>();
    bgemm_alpha<<<280, 128>>>();
    chol_all<<<20, 256>>>();
    solve_all<<<170, 256>>>();
    epilogue<<<320, 256>>>(Xt, W2, out);
}